// round 1
// baseline (speedup 1.0000x reference)
#include <cuda_runtime.h>
#include <cstddef>

// Problem constants
#define BATCH   2
#define SEQ     2048
#define DMODEL  1024
#define NH      16
#define DH      64
#define MTOT    (BATCH * SEQ)        // 4096 rows

// ---------------------------------------------------------------------------
// Scratch (device globals; no allocations allowed)
// ---------------------------------------------------------------------------
__device__ float g_Q [MTOT * DMODEL];
__device__ float g_K [MTOT * DMODEL];
__device__ float g_V [MTOT * DMODEL];
__device__ float g_AO[MTOT * DMODEL];

// ---------------------------------------------------------------------------
// GEMM: C[M,N] = A[M,K] @ B[N,K]^T + bias[N]
// A row-major [M,K], B row-major [N,K] (nn.Linear weight layout).
// 128x128 block tile, BK=16, 256 threads, 8x8 per-thread microtile.
// ---------------------------------------------------------------------------
__global__ __launch_bounds__(256)
void gemm_bias_kernel(const float* __restrict__ A,
                      const float* __restrict__ B,
                      const float* __restrict__ bias,
                      float* __restrict__ C,
                      int M, int N, int K)
{
    __shared__ float As[16][128];
    __shared__ float Bs[16][128];

    const int bm = blockIdx.y * 128;
    const int bn = blockIdx.x * 128;
    const int t  = threadIdx.x;
    const int tm = t >> 4;        // 0..15
    const int tn = t & 15;        // 0..15

    float acc[8][8];
#pragma unroll
    for (int i = 0; i < 8; i++)
#pragma unroll
        for (int j = 0; j < 8; j++) acc[i][j] = 0.0f;

    const int lrow = t >> 2;           // 0..63
    const int lcol = (t & 3) * 4;      // 0,4,8,12

    for (int k0 = 0; k0 < K; k0 += 16) {
#pragma unroll
        for (int r = 0; r < 2; r++) {
            const int row = lrow + r * 64;
            float4 va = *(const float4*)&A[(size_t)(bm + row) * K + k0 + lcol];
            As[lcol + 0][row] = va.x;
            As[lcol + 1][row] = va.y;
            As[lcol + 2][row] = va.z;
            As[lcol + 3][row] = va.w;
            float4 vb = *(const float4*)&B[(size_t)(bn + row) * K + k0 + lcol];
            Bs[lcol + 0][row] = vb.x;
            Bs[lcol + 1][row] = vb.y;
            Bs[lcol + 2][row] = vb.z;
            Bs[lcol + 3][row] = vb.w;
        }
        __syncthreads();

#pragma unroll
        for (int k = 0; k < 16; k++) {
            float a[8], b[8];
#pragma unroll
            for (int i = 0; i < 8; i++) a[i] = As[k][tm * 8 + i];
#pragma unroll
            for (int j = 0; j < 8; j++) b[j] = Bs[k][tn * 8 + j];
#pragma unroll
            for (int i = 0; i < 8; i++)
#pragma unroll
                for (int j = 0; j < 8; j++)
                    acc[i][j] += a[i] * b[j];
        }
        __syncthreads();
    }

#pragma unroll
    for (int i = 0; i < 8; i++) {
        const int row = bm + tm * 8 + i;
#pragma unroll
        for (int jv = 0; jv < 2; jv++) {
            const int col = bn + tn * 8 + jv * 4;
            float4 v;
            v.x = acc[i][jv * 4 + 0] + bias[col + 0];
            v.y = acc[i][jv * 4 + 1] + bias[col + 1];
            v.z = acc[i][jv * 4 + 2] + bias[col + 2];
            v.w = acc[i][jv * 4 + 3] + bias[col + 3];
            *(float4*)&C[(size_t)row * N + col] = v;
        }
    }
}

// ---------------------------------------------------------------------------
// Causal (no-softmax) attention:
//   O[b,h,q,:] = sum_{s<=q} (Q[b,h,q,:].K[b,h,s,:]) * V[b,h,s,:]
// Heads live as 64-wide column slices of the [4096,1024] Q/K/V buffers.
// Per CTA: one (b, h, 128-row q block). Flash-style loop over key blocks.
// smem: Qs[64][128] (d-major), Ks[64][128] (d-major), Vs[128][64],
//       Ss[128][129] stored n-major (Ss[n][m]).
// ---------------------------------------------------------------------------
#define ATTN_SMEM_FLOATS (64*128 + 64*128 + 128*64 + 128*129)
#define ATTN_SMEM_BYTES  (ATTN_SMEM_FLOATS * 4)

__global__ __launch_bounds__(256)
void attn_kernel(const float* __restrict__ Q,
                 const float* __restrict__ K,
                 const float* __restrict__ V,
                 float* __restrict__ O)
{
    extern __shared__ float smem[];
    float* Qs = smem;                    // [64][128]
    float* Ks = Qs + 64 * 128;           // [64][128]
    float* Vs = Ks + 64 * 128;           // [128][64]
    float* Ss = Vs + 128 * 64;           // [128][129], Ss[n][m]

    const int qb = blockIdx.x;           // 0..15
    const int h  = blockIdx.y;           // 0..15
    const int b  = blockIdx.z;           // 0..1

    const int t  = threadIdx.x;
    const int tx = t & 15;               // 0..15
    const int ty = t >> 4;               // 0..15

    const size_t headoff = (size_t)b * SEQ * DMODEL + (size_t)h * DH;
    const float* Qbase = Q + headoff;
    const float* Kbase = K + headoff;
    const float* Vbase = V + headoff;

    // Load Q tile -> Qs[d][m]
    {
        const int row   = t >> 1;             // 0..127
        const int cbase = (t & 1) * 32;       // 0 or 32
        const float* src = Qbase + (size_t)(qb * 128 + row) * DMODEL;
#pragma unroll
        for (int c = 0; c < 8; c++) {
            const int d = cbase + c * 4;
            float4 v = *(const float4*)&src[d];
            Qs[(d + 0) * 128 + row] = v.x;
            Qs[(d + 1) * 128 + row] = v.y;
            Qs[(d + 2) * 128 + row] = v.z;
            Qs[(d + 3) * 128 + row] = v.w;
        }
    }

    float o[8][4];
#pragma unroll
    for (int i = 0; i < 8; i++)
#pragma unroll
        for (int j = 0; j < 4; j++) o[i][j] = 0.0f;

    for (int kb = 0; kb <= qb; kb++) {
        __syncthreads();   // previous iter done with Ks/Vs (and Q load visible path)

        // Load K tile -> Ks[d][n], V tile -> Vs[n][d]
        {
            const int row   = t >> 1;
            const int cbase = (t & 1) * 32;
            const float* ksrc = Kbase + (size_t)(kb * 128 + row) * DMODEL;
            const float* vsrc = Vbase + (size_t)(kb * 128 + row) * DMODEL;
#pragma unroll
            for (int c = 0; c < 8; c++) {
                const int d = cbase + c * 4;
                float4 v = *(const float4*)&ksrc[d];
                Ks[(d + 0) * 128 + row] = v.x;
                Ks[(d + 1) * 128 + row] = v.y;
                Ks[(d + 2) * 128 + row] = v.z;
                Ks[(d + 3) * 128 + row] = v.w;
                float4 w = *(const float4*)&vsrc[d];
                *(float4*)&Vs[row * 64 + d] = w;
            }
        }
        __syncthreads();

        // Phase 1: S[m][n] = sum_d Q[m][d]*K[n][d];  m = ty*8+i, n = tx*8+j
        float s[8][8];
#pragma unroll
        for (int i = 0; i < 8; i++)
#pragma unroll
            for (int j = 0; j < 8; j++) s[i][j] = 0.0f;

#pragma unroll 4
        for (int d = 0; d < 64; d++) {
            float a[8], c_[8];
#pragma unroll
            for (int i = 0; i < 8; i++) a[i]  = Qs[d * 128 + ty * 8 + i];
#pragma unroll
            for (int j = 0; j < 8; j++) c_[j] = Ks[d * 128 + tx * 8 + j];
#pragma unroll
            for (int i = 0; i < 8; i++)
#pragma unroll
                for (int j = 0; j < 8; j++)
                    s[i][j] += a[i] * c_[j];
        }

        if (kb == qb) {
            // Diagonal block: keep only n <= m
#pragma unroll
            for (int i = 0; i < 8; i++)
#pragma unroll
                for (int j = 0; j < 8; j++)
                    if (tx * 8 + j > ty * 8 + i) s[i][j] = 0.0f;
        }

        // Store S transposed: Ss[n][m]
#pragma unroll
        for (int j = 0; j < 8; j++)
#pragma unroll
            for (int i = 0; i < 8; i++)
                Ss[(tx * 8 + j) * 129 + ty * 8 + i] = s[i][j];
        __syncthreads();

        // Phase 2: O[m][d] += sum_n S[m][n]*V[n][d];  m = ty*8+i, d = tx*4+j
#pragma unroll 4
        for (int n = 0; n < 128; n++) {
            float sv[8];
#pragma unroll
            for (int i = 0; i < 8; i++) sv[i] = Ss[n * 129 + ty * 8 + i];
            float4 vv = *(const float4*)&Vs[n * 64 + tx * 4];
#pragma unroll
            for (int i = 0; i < 8; i++) {
                o[i][0] += sv[i] * vv.x;
                o[i][1] += sv[i] * vv.y;
                o[i][2] += sv[i] * vv.z;
                o[i][3] += sv[i] * vv.w;
            }
        }
    }

    // Epilogue: write O tile back into the [4096,1024] concat-head layout.
    float* Obase = O + headoff;
#pragma unroll
    for (int i = 0; i < 8; i++) {
        const int row = qb * 128 + ty * 8 + i;
        float4 v;
        v.x = o[i][0]; v.y = o[i][1]; v.z = o[i][2]; v.w = o[i][3];
        *(float4*)&Obase[(size_t)row * DMODEL + tx * 4] = v;
    }
}

// ---------------------------------------------------------------------------
// Launch
// ---------------------------------------------------------------------------
extern "C" void kernel_launch(void* const* d_in, const int* in_sizes, int n_in,
                              void* d_out, int out_size)
{
    const float* x    = (const float*)d_in[0];
    const float* wq_w = (const float*)d_in[1];
    const float* wq_b = (const float*)d_in[2];
    const float* wk_w = (const float*)d_in[3];
    const float* wk_b = (const float*)d_in[4];
    const float* wv_w = (const float*)d_in[5];
    const float* wv_b = (const float*)d_in[6];
    const float* wo_w = (const float*)d_in[7];
    const float* wo_b = (const float*)d_in[8];
    float* out = (float*)d_out;

    float *Qp, *Kp, *Vp, *AOp;
    cudaGetSymbolAddress((void**)&Qp,  g_Q);
    cudaGetSymbolAddress((void**)&Kp,  g_K);
    cudaGetSymbolAddress((void**)&Vp,  g_V);
    cudaGetSymbolAddress((void**)&AOp, g_AO);

    cudaFuncSetAttribute(attn_kernel,
                         cudaFuncAttributeMaxDynamicSharedMemorySize,
                         ATTN_SMEM_BYTES);

    dim3 ggrid(DMODEL / 128, MTOT / 128);   // (8, 32)
    gemm_bias_kernel<<<ggrid, 256>>>(x, wq_w, wq_b, Qp, MTOT, DMODEL, DMODEL);
    gemm_bias_kernel<<<ggrid, 256>>>(x, wk_w, wk_b, Kp, MTOT, DMODEL, DMODEL);
    gemm_bias_kernel<<<ggrid, 256>>>(x, wv_w, wv_b, Vp, MTOT, DMODEL, DMODEL);

    dim3 agrid(SEQ / 128, NH, BATCH);       // (16, 16, 2)
    attn_kernel<<<agrid, 256, ATTN_SMEM_BYTES>>>(Qp, Kp, Vp, AOp);

    gemm_bias_kernel<<<ggrid, 256>>>(AOp, wo_w, wo_b, out, MTOT, DMODEL, DMODEL);
}

// round 5
// speedup vs baseline: 2.2224x; 2.2224x over previous
#include <cuda_runtime.h>
#include <cuda_bf16.h>
#include <cstdint>
#include <cstddef>

// Problem constants
#define BATCH   2
#define SEQ     2048
#define DMODEL  1024
#define NH      16
#define DH      64
#define MTOT    (BATCH * SEQ)        // 4096 rows

// ---------------------------------------------------------------------------
// Scratch (device globals; no allocations allowed)
// ---------------------------------------------------------------------------
__device__ float g_Q [MTOT * DMODEL];
__device__ float g_K [MTOT * DMODEL];
__device__ float g_V [MTOT * DMODEL];
__device__ float g_AO[MTOT * DMODEL];

// ---------------------------------------------------------------------------
// mma.sync helpers (portable sm_80+ path; sm_100 target has no tcgen05)
// ---------------------------------------------------------------------------
__device__ __forceinline__ void mma_bf16(float* c, const uint32_t* a, const uint32_t* b) {
    asm volatile(
        "mma.sync.aligned.m16n8k16.row.col.f32.bf16.bf16.f32 "
        "{%0,%1,%2,%3}, {%4,%5,%6,%7}, {%8,%9}, {%0,%1,%2,%3};"
        : "+f"(c[0]), "+f"(c[1]), "+f"(c[2]), "+f"(c[3])
        : "r"(a[0]), "r"(a[1]), "r"(a[2]), "r"(a[3]),
          "r"(b[0]), "r"(b[1]));
}

__device__ __forceinline__ uint32_t pack2_bf16(float a, float b) {
    __nv_bfloat162 t = __floats2bfloat162_rn(a, b);
    return *(uint32_t*)&t;
}

__device__ __forceinline__ float bf16_hi(float x) {
    return __bfloat162float(__float2bfloat16(x));
}

// ===========================================================================
// Split-bf16 tensor-core GEMM: C[M,N] = A[M,K] @ B[N,K]^T + bias[N]
// 128x128 CTA tile, BK=64, 256 threads (8 warps: 4M x 2N, warp tile 32x64).
// smem tiles: Ahi/Alo/Bhi/Blo, bf16 [128][64] padded to stride 72 halves.
// C ~= Ahi*Bhi + Ahi*Blo + Alo*Bhi   (fp32 accum in registers)
// ===========================================================================
#define GS 72                                    // smem row stride (halves)
#define GEMM_TILE_H (128 * GS)                   // halves per tile
#define GEMM_SMEM_B (4 * GEMM_TILE_H * 2)        // 73728 bytes

__global__ __launch_bounds__(256, 1)
void mma_gemm_kernel(const float* __restrict__ A,
                     const float* __restrict__ B,
                     const float* __restrict__ bias,
                     float* __restrict__ C,
                     int M, int N, int K)
{
    extern __shared__ __nv_bfloat16 sm[];
    __nv_bfloat16* Ahi = sm;
    __nv_bfloat16* Alo = sm + GEMM_TILE_H;
    __nv_bfloat16* Bhi = sm + 2 * GEMM_TILE_H;
    __nv_bfloat16* Blo = sm + 3 * GEMM_TILE_H;

    const int t    = threadIdx.x;
    const int wid  = t >> 5;
    const int lane = t & 31;
    const int g    = lane >> 2;      // 0..7
    const int tq   = lane & 3;       // 0..3
    const int wm   = wid >> 1;       // 0..3
    const int wn   = wid & 1;        // 0..1
    const int m0   = wm * 32;
    const int n0   = wn * 64;

    const int bm = blockIdx.y * 128;
    const int bn = blockIdx.x * 128;

    float acc[2][8][4];
#pragma unroll
    for (int mi = 0; mi < 2; mi++)
#pragma unroll
        for (int ni = 0; ni < 8; ni++)
#pragma unroll
            for (int e = 0; e < 4; e++) acc[mi][ni][e] = 0.0f;

    for (int chunk = 0; chunk < K / 64; chunk++) {
        const int k0 = chunk * 64;

        // Load + split A,B tiles: 128 rows x 64 floats each; 8 float4/thread each
#pragma unroll
        for (int i = 0; i < 8; i++) {
            const int l   = i * 256 + t;
            const int row = l >> 4;
            const int c4  = l & 15;
            const int so  = row * GS + c4 * 4;

            float4 va = *(const float4*)&A[(size_t)(bm + row) * K + k0 + c4 * 4];
            uint2 hi, lo;
            hi.x = pack2_bf16(va.x, va.y);
            hi.y = pack2_bf16(va.z, va.w);
            lo.x = pack2_bf16(va.x - bf16_hi(va.x), va.y - bf16_hi(va.y));
            lo.y = pack2_bf16(va.z - bf16_hi(va.z), va.w - bf16_hi(va.w));
            *(uint2*)&Ahi[so] = hi;
            *(uint2*)&Alo[so] = lo;

            float4 vb = *(const float4*)&B[(size_t)(bn + row) * K + k0 + c4 * 4];
            hi.x = pack2_bf16(vb.x, vb.y);
            hi.y = pack2_bf16(vb.z, vb.w);
            lo.x = pack2_bf16(vb.x - bf16_hi(vb.x), vb.y - bf16_hi(vb.y));
            lo.y = pack2_bf16(vb.z - bf16_hi(vb.z), vb.w - bf16_hi(vb.w));
            *(uint2*)&Bhi[so] = hi;
            *(uint2*)&Blo[so] = lo;
        }
        __syncthreads();

#pragma unroll
        for (int ks = 0; ks < 4; ks++) {
            const int kk = ks * 16;

            uint32_t ah[2][4], al[2][4];
#pragma unroll
            for (int mi = 0; mi < 2; mi++) {
                const int r = m0 + mi * 16 + g;
                ah[mi][0] = *(const uint32_t*)&Ahi[r * GS + kk + 2 * tq];
                ah[mi][1] = *(const uint32_t*)&Ahi[(r + 8) * GS + kk + 2 * tq];
                ah[mi][2] = *(const uint32_t*)&Ahi[r * GS + kk + 8 + 2 * tq];
                ah[mi][3] = *(const uint32_t*)&Ahi[(r + 8) * GS + kk + 8 + 2 * tq];
                al[mi][0] = *(const uint32_t*)&Alo[r * GS + kk + 2 * tq];
                al[mi][1] = *(const uint32_t*)&Alo[(r + 8) * GS + kk + 2 * tq];
                al[mi][2] = *(const uint32_t*)&Alo[r * GS + kk + 8 + 2 * tq];
                al[mi][3] = *(const uint32_t*)&Alo[(r + 8) * GS + kk + 8 + 2 * tq];
            }

            uint32_t bh[8][2], bl[8][2];
#pragma unroll
            for (int ni = 0; ni < 8; ni++) {
                const int rn = n0 + ni * 8 + g;
                bh[ni][0] = *(const uint32_t*)&Bhi[rn * GS + kk + 2 * tq];
                bh[ni][1] = *(const uint32_t*)&Bhi[rn * GS + kk + 8 + 2 * tq];
                bl[ni][0] = *(const uint32_t*)&Blo[rn * GS + kk + 2 * tq];
                bl[ni][1] = *(const uint32_t*)&Blo[rn * GS + kk + 8 + 2 * tq];
            }

#pragma unroll
            for (int mi = 0; mi < 2; mi++)
#pragma unroll
                for (int ni = 0; ni < 8; ni++) {
                    mma_bf16(acc[mi][ni], ah[mi], bh[ni]);
                    mma_bf16(acc[mi][ni], ah[mi], bl[ni]);
                    mma_bf16(acc[mi][ni], al[mi], bh[ni]);
                }
        }
        __syncthreads();
    }

    // Epilogue
#pragma unroll
    for (int mi = 0; mi < 2; mi++) {
        const int r0 = bm + m0 + mi * 16 + g;
#pragma unroll
        for (int ni = 0; ni < 8; ni++) {
            const int col = bn + n0 + ni * 8 + 2 * tq;
            float2 v0, v1;
            v0.x = acc[mi][ni][0] + bias[col];
            v0.y = acc[mi][ni][1] + bias[col + 1];
            v1.x = acc[mi][ni][2] + bias[col];
            v1.y = acc[mi][ni][3] + bias[col + 1];
            *(float2*)&C[(size_t)r0 * N + col]       = v0;
            *(float2*)&C[(size_t)(r0 + 8) * N + col] = v1;
        }
    }
}

// ===========================================================================
// Split-bf16 tensor-core causal attention (no softmax):
//   O[q,:] = sum_{s<=q} (Q[q,:].K[s,:]) V[s,:]
// Per CTA: one (b,h,128-q-block). 8 warps (4M x 2N).
// Phase 1: S = Q K^T via mma (warp tile 32x64 of S), mask diag, split to smem.
// Phase 2: O += S V via mma (warp tile 32x32 of O), fp32 accum across blocks.
// ===========================================================================
#define AS 72                         // Q/K row stride (halves), 64 data cols
#define SS 136                        // S/Vt row stride (halves), 128 data cols
#define QK_TILE_H (128 * AS)          // 9216 halves
#define VT_TILE_H (64 * SS)           // 8704 halves
#define S_TILE_H  (128 * SS)          // 17408 halves
#define ATTN_SMEM_B ((4 * QK_TILE_H + 2 * VT_TILE_H + 2 * S_TILE_H) * 2)  // 178176

__global__ __launch_bounds__(256, 1)
void mma_attn_kernel(const float* __restrict__ Q,
                     const float* __restrict__ K,
                     const float* __restrict__ V,
                     float* __restrict__ O)
{
    extern __shared__ __nv_bfloat16 sm[];
    __nv_bfloat16* Qhi  = sm;
    __nv_bfloat16* Qlo  = Qhi + QK_TILE_H;
    __nv_bfloat16* Khi  = Qlo + QK_TILE_H;
    __nv_bfloat16* Klo  = Khi + QK_TILE_H;
    __nv_bfloat16* Vthi = Klo + QK_TILE_H;
    __nv_bfloat16* Vtlo = Vthi + VT_TILE_H;
    __nv_bfloat16* Shi  = Vtlo + VT_TILE_H;
    __nv_bfloat16* Slo  = Shi + S_TILE_H;

    const int qb = blockIdx.x;
    const int h  = blockIdx.y;
    const int b  = blockIdx.z;

    const int t    = threadIdx.x;
    const int wid  = t >> 5;
    const int lane = t & 31;
    const int g    = lane >> 2;
    const int tq   = lane & 3;
    const int wm   = wid >> 1;        // 0..3
    const int wn   = wid & 1;         // 0..1
    const int m0   = wm * 32;

    const size_t headoff = (size_t)b * SEQ * DMODEL + (size_t)h * DH;
    const float* Qbase = Q + headoff;
    const float* Kbase = K + headoff;
    const float* Vbase = V + headoff;

    // Load Q tile (128x64 fp32) -> Qhi/Qlo, row-major stride AS
    {
        const int row   = t >> 1;
        const int cbase = (t & 1) * 32;
        const float* src = Qbase + (size_t)(qb * 128 + row) * DMODEL;
#pragma unroll
        for (int c = 0; c < 8; c++) {
            const int d = cbase + c * 4;
            float4 v = *(const float4*)&src[d];
            uint2 hi, lo;
            hi.x = pack2_bf16(v.x, v.y);
            hi.y = pack2_bf16(v.z, v.w);
            lo.x = pack2_bf16(v.x - bf16_hi(v.x), v.y - bf16_hi(v.y));
            lo.y = pack2_bf16(v.z - bf16_hi(v.z), v.w - bf16_hi(v.w));
            *(uint2*)&Qhi[row * AS + d] = hi;
            *(uint2*)&Qlo[row * AS + d] = lo;
        }
    }

    // O accumulators: warp tile 32 rows x 32 cols (d0 = wn*32)
    const int d0 = wn * 32;
    float o[2][4][4];
#pragma unroll
    for (int mi = 0; mi < 2; mi++)
#pragma unroll
        for (int ni = 0; ni < 4; ni++)
#pragma unroll
            for (int e = 0; e < 4; e++) o[mi][ni][e] = 0.0f;

    for (int kb = 0; kb <= qb; kb++) {
        __syncthreads();   // prior iter done with K/V/S

        // Load K (row-major) and V (transposed) tiles
        {
            const int row   = t >> 1;
            const int cbase = (t & 1) * 32;
            const float* ksrc = Kbase + (size_t)(kb * 128 + row) * DMODEL;
            const float* vsrc = Vbase + (size_t)(kb * 128 + row) * DMODEL;
#pragma unroll
            for (int c = 0; c < 8; c++) {
                const int d = cbase + c * 4;
                float4 v = *(const float4*)&ksrc[d];
                uint2 hi, lo;
                hi.x = pack2_bf16(v.x, v.y);
                hi.y = pack2_bf16(v.z, v.w);
                lo.x = pack2_bf16(v.x - bf16_hi(v.x), v.y - bf16_hi(v.y));
                lo.y = pack2_bf16(v.z - bf16_hi(v.z), v.w - bf16_hi(v.w));
                *(uint2*)&Khi[row * AS + d] = hi;
                *(uint2*)&Klo[row * AS + d] = lo;

                float4 w = *(const float4*)&vsrc[d];
                Vthi[(d + 0) * SS + row] = __float2bfloat16(w.x);
                Vthi[(d + 1) * SS + row] = __float2bfloat16(w.y);
                Vthi[(d + 2) * SS + row] = __float2bfloat16(w.z);
                Vthi[(d + 3) * SS + row] = __float2bfloat16(w.w);
                Vtlo[(d + 0) * SS + row] = __float2bfloat16(w.x - bf16_hi(w.x));
                Vtlo[(d + 1) * SS + row] = __float2bfloat16(w.y - bf16_hi(w.y));
                Vtlo[(d + 2) * SS + row] = __float2bfloat16(w.z - bf16_hi(w.z));
                Vtlo[(d + 3) * SS + row] = __float2bfloat16(w.w - bf16_hi(w.w));
            }
        }
        __syncthreads();

        // ---- Phase 1: S subtile [32 x 64] at (m0, n0s = wn*64) ----
        {
            const int n0s = wn * 64;
            float s[2][8][4];
#pragma unroll
            for (int mi = 0; mi < 2; mi++)
#pragma unroll
                for (int ni = 0; ni < 8; ni++)
#pragma unroll
                    for (int e = 0; e < 4; e++) s[mi][ni][e] = 0.0f;

#pragma unroll
            for (int ks = 0; ks < 4; ks++) {
                const int kk = ks * 16;
                uint32_t ah[2][4], al[2][4];
#pragma unroll
                for (int mi = 0; mi < 2; mi++) {
                    const int r = m0 + mi * 16 + g;
                    ah[mi][0] = *(const uint32_t*)&Qhi[r * AS + kk + 2 * tq];
                    ah[mi][1] = *(const uint32_t*)&Qhi[(r + 8) * AS + kk + 2 * tq];
                    ah[mi][2] = *(const uint32_t*)&Qhi[r * AS + kk + 8 + 2 * tq];
                    ah[mi][3] = *(const uint32_t*)&Qhi[(r + 8) * AS + kk + 8 + 2 * tq];
                    al[mi][0] = *(const uint32_t*)&Qlo[r * AS + kk + 2 * tq];
                    al[mi][1] = *(const uint32_t*)&Qlo[(r + 8) * AS + kk + 2 * tq];
                    al[mi][2] = *(const uint32_t*)&Qlo[r * AS + kk + 8 + 2 * tq];
                    al[mi][3] = *(const uint32_t*)&Qlo[(r + 8) * AS + kk + 8 + 2 * tq];
                }
                uint32_t bh[8][2], bl[8][2];
#pragma unroll
                for (int ni = 0; ni < 8; ni++) {
                    const int rn = n0s + ni * 8 + g;
                    bh[ni][0] = *(const uint32_t*)&Khi[rn * AS + kk + 2 * tq];
                    bh[ni][1] = *(const uint32_t*)&Khi[rn * AS + kk + 8 + 2 * tq];
                    bl[ni][0] = *(const uint32_t*)&Klo[rn * AS + kk + 2 * tq];
                    bl[ni][1] = *(const uint32_t*)&Klo[rn * AS + kk + 8 + 2 * tq];
                }
#pragma unroll
                for (int mi = 0; mi < 2; mi++)
#pragma unroll
                    for (int ni = 0; ni < 8; ni++) {
                        mma_bf16(s[mi][ni], ah[mi], bh[ni]);
                        mma_bf16(s[mi][ni], ah[mi], bl[ni]);
                        mma_bf16(s[mi][ni], al[mi], bh[ni]);
                    }
            }

            // Mask diagonal block (keep col <= row), split, store to smem
#pragma unroll
            for (int mi = 0; mi < 2; mi++) {
                const int r = m0 + mi * 16 + g;
#pragma unroll
                for (int ni = 0; ni < 8; ni++) {
                    const int ccol = n0s + ni * 8 + 2 * tq;
                    float v0 = s[mi][ni][0], v1 = s[mi][ni][1];
                    float v2 = s[mi][ni][2], v3 = s[mi][ni][3];
                    if (kb == qb) {
                        if (ccol     > r)     v0 = 0.0f;
                        if (ccol + 1 > r)     v1 = 0.0f;
                        if (ccol     > r + 8) v2 = 0.0f;
                        if (ccol + 1 > r + 8) v3 = 0.0f;
                    }
                    float h0 = bf16_hi(v0), h1 = bf16_hi(v1);
                    float h2 = bf16_hi(v2), h3 = bf16_hi(v3);
                    *(uint32_t*)&Shi[r * SS + ccol]       = pack2_bf16(v0, v1);
                    *(uint32_t*)&Slo[r * SS + ccol]       = pack2_bf16(v0 - h0, v1 - h1);
                    *(uint32_t*)&Shi[(r + 8) * SS + ccol] = pack2_bf16(v2, v3);
                    *(uint32_t*)&Slo[(r + 8) * SS + ccol] = pack2_bf16(v2 - h2, v3 - h3);
                }
            }
        }
        __syncthreads();

        // ---- Phase 2: O[32x32] += S[32x128] @ V[128x32] ----
#pragma unroll
        for (int ks = 0; ks < 8; ks++) {
            const int kk = ks * 16;
            uint32_t ah[2][4], al[2][4];
#pragma unroll
            for (int mi = 0; mi < 2; mi++) {
                const int r = m0 + mi * 16 + g;
                ah[mi][0] = *(const uint32_t*)&Shi[r * SS + kk + 2 * tq];
                ah[mi][1] = *(const uint32_t*)&Shi[(r + 8) * SS + kk + 2 * tq];
                ah[mi][2] = *(const uint32_t*)&Shi[r * SS + kk + 8 + 2 * tq];
                ah[mi][3] = *(const uint32_t*)&Shi[(r + 8) * SS + kk + 8 + 2 * tq];
                al[mi][0] = *(const uint32_t*)&Slo[r * SS + kk + 2 * tq];
                al[mi][1] = *(const uint32_t*)&Slo[(r + 8) * SS + kk + 2 * tq];
                al[mi][2] = *(const uint32_t*)&Slo[r * SS + kk + 8 + 2 * tq];
                al[mi][3] = *(const uint32_t*)&Slo[(r + 8) * SS + kk + 8 + 2 * tq];
            }
            uint32_t bh[4][2], bl[4][2];
#pragma unroll
            for (int ni = 0; ni < 4; ni++) {
                const int rd = d0 + ni * 8 + g;
                bh[ni][0] = *(const uint32_t*)&Vthi[rd * SS + kk + 2 * tq];
                bh[ni][1] = *(const uint32_t*)&Vthi[rd * SS + kk + 8 + 2 * tq];
                bl[ni][0] = *(const uint32_t*)&Vtlo[rd * SS + kk + 2 * tq];
                bl[ni][1] = *(const uint32_t*)&Vtlo[rd * SS + kk + 8 + 2 * tq];
            }
#pragma unroll
            for (int mi = 0; mi < 2; mi++)
#pragma unroll
                for (int ni = 0; ni < 4; ni++) {
                    mma_bf16(o[mi][ni], ah[mi], bh[ni]);
                    mma_bf16(o[mi][ni], ah[mi], bl[ni]);
                    mma_bf16(o[mi][ni], al[mi], bh[ni]);
                }
        }
    }

    // Epilogue: write O tile to concat-head layout
    float* Obase = O + headoff;
#pragma unroll
    for (int mi = 0; mi < 2; mi++) {
        const int r = qb * 128 + m0 + mi * 16 + g;
#pragma unroll
        for (int ni = 0; ni < 4; ni++) {
            const int col = d0 + ni * 8 + 2 * tq;
            float2 v0, v1;
            v0.x = o[mi][ni][0]; v0.y = o[mi][ni][1];
            v1.x = o[mi][ni][2]; v1.y = o[mi][ni][3];
            *(float2*)&Obase[(size_t)r * DMODEL + col]       = v0;
            *(float2*)&Obase[(size_t)(r + 8) * DMODEL + col] = v1;
        }
    }
}

// ---------------------------------------------------------------------------
// Launch
// ---------------------------------------------------------------------------
extern "C" void kernel_launch(void* const* d_in, const int* in_sizes, int n_in,
                              void* d_out, int out_size)
{
    const float* x    = (const float*)d_in[0];
    const float* wq_w = (const float*)d_in[1];
    const float* wq_b = (const float*)d_in[2];
    const float* wk_w = (const float*)d_in[3];
    const float* wk_b = (const float*)d_in[4];
    const float* wv_w = (const float*)d_in[5];
    const float* wv_b = (const float*)d_in[6];
    const float* wo_w = (const float*)d_in[7];
    const float* wo_b = (const float*)d_in[8];
    float* out = (float*)d_out;

    float *Qp, *Kp, *Vp, *AOp;
    cudaGetSymbolAddress((void**)&Qp,  g_Q);
    cudaGetSymbolAddress((void**)&Kp,  g_K);
    cudaGetSymbolAddress((void**)&Vp,  g_V);
    cudaGetSymbolAddress((void**)&AOp, g_AO);

    cudaFuncSetAttribute(mma_gemm_kernel,
                         cudaFuncAttributeMaxDynamicSharedMemorySize, GEMM_SMEM_B);
    cudaFuncSetAttribute(mma_attn_kernel,
                         cudaFuncAttributeMaxDynamicSharedMemorySize, ATTN_SMEM_B);

    dim3 ggrid(DMODEL / 128, MTOT / 128);   // (8, 32)
    mma_gemm_kernel<<<ggrid, 256, GEMM_SMEM_B>>>(x, wq_w, wq_b, Qp, MTOT, DMODEL, DMODEL);
    mma_gemm_kernel<<<ggrid, 256, GEMM_SMEM_B>>>(x, wk_w, wk_b, Kp, MTOT, DMODEL, DMODEL);
    mma_gemm_kernel<<<ggrid, 256, GEMM_SMEM_B>>>(x, wv_w, wv_b, Vp, MTOT, DMODEL, DMODEL);

    dim3 agrid(SEQ / 128, NH, BATCH);       // (16, 16, 2)
    mma_attn_kernel<<<agrid, 256, ATTN_SMEM_B>>>(Qp, Kp, Vp, AOp);

    mma_gemm_kernel<<<ggrid, 256, GEMM_SMEM_B>>>(AOp, wo_w, wo_b, out, MTOT, DMODEL, DMODEL);
}

// round 6
// speedup vs baseline: 2.8193x; 1.2686x over previous
#include <cuda_runtime.h>
#include <cuda_bf16.h>
#include <cstdint>
#include <cstddef>

// Problem constants
#define BATCH   2
#define SEQ     2048
#define DMODEL  1024
#define NH      16
#define DH      64
#define MTOT    (BATCH * SEQ)        // 4096 rows

// ---------------------------------------------------------------------------
// Scratch (device globals; no allocations allowed)
// ---------------------------------------------------------------------------
__device__ __nv_bfloat16 g_xhi [MTOT * DMODEL];
__device__ __nv_bfloat16 g_xlo [MTOT * DMODEL];
__device__ __nv_bfloat16 g_whi [4][DMODEL * DMODEL];
__device__ __nv_bfloat16 g_wlo [4][DMODEL * DMODEL];
__device__ __nv_bfloat16 g_Qhi [MTOT * DMODEL];
__device__ __nv_bfloat16 g_Qlo [MTOT * DMODEL];
__device__ __nv_bfloat16 g_Khi [MTOT * DMODEL];
__device__ __nv_bfloat16 g_Klo [MTOT * DMODEL];
__device__ __nv_bfloat16 g_Vhi [MTOT * DMODEL];
__device__ __nv_bfloat16 g_Vlo [MTOT * DMODEL];
__device__ __nv_bfloat16 g_AOhi[MTOT * DMODEL];
__device__ __nv_bfloat16 g_AOlo[MTOT * DMODEL];

// ---------------------------------------------------------------------------
// Helpers
// ---------------------------------------------------------------------------
__device__ __forceinline__ void mma_bf16(float* c, const uint32_t* a, const uint32_t* b) {
    asm volatile(
        "mma.sync.aligned.m16n8k16.row.col.f32.bf16.bf16.f32 "
        "{%0,%1,%2,%3}, {%4,%5,%6,%7}, {%8,%9}, {%0,%1,%2,%3};"
        : "+f"(c[0]), "+f"(c[1]), "+f"(c[2]), "+f"(c[3])
        : "r"(a[0]), "r"(a[1]), "r"(a[2]), "r"(a[3]),
          "r"(b[0]), "r"(b[1]));
}

__device__ __forceinline__ uint32_t pack2_bf16(float a, float b) {
    __nv_bfloat162 t = __floats2bfloat162_rn(a, b);
    return *(uint32_t*)&t;
}
__device__ __forceinline__ float bf16_hi(float x) {
    return __bfloat162float(__float2bfloat16(x));
}

__device__ __forceinline__ uint32_t smem_u32(const void* p) {
    uint32_t a;
    asm("{ .reg .u64 t; cvta.to.shared.u64 t, %1; cvt.u32.u64 %0, t; }"
        : "=r"(a) : "l"(p));
    return a;
}

__device__ __forceinline__ void cp16(uint32_t dst, const void* src) {
    asm volatile("cp.async.cg.shared.global [%0], [%1], 16;" :: "r"(dst), "l"(src));
}
#define CP_COMMIT() asm volatile("cp.async.commit_group;" ::: "memory")
#define CP_WAIT(n)  asm volatile("cp.async.wait_group %0;" :: "n"(n) : "memory")

__device__ __forceinline__ void ldsm_x4(uint32_t* r, uint32_t addr) {
    asm volatile("ldmatrix.sync.aligned.m8n8.x4.shared.b16 {%0,%1,%2,%3}, [%4];"
        : "=r"(r[0]), "=r"(r[1]), "=r"(r[2]), "=r"(r[3]) : "r"(addr));
}
__device__ __forceinline__ void ldsm_x4_t(uint32_t* r, uint32_t addr) {
    asm volatile("ldmatrix.sync.aligned.m8n8.x4.trans.shared.b16 {%0,%1,%2,%3}, [%4];"
        : "=r"(r[0]), "=r"(r[1]), "=r"(r[2]), "=r"(r[3]) : "r"(addr));
}

// ---------------------------------------------------------------------------
// Split kernel: fp32 -> bf16 hi + bf16 lo residual
// ---------------------------------------------------------------------------
__global__ void split_kernel(const float* __restrict__ src,
                             __nv_bfloat16* __restrict__ hi,
                             __nv_bfloat16* __restrict__ lo, int n4)
{
    int i = blockIdx.x * blockDim.x + threadIdx.x;
    if (i >= n4) return;
    float4 v = ((const float4*)src)[i];
    uint2 h, l;
    h.x = pack2_bf16(v.x, v.y);
    h.y = pack2_bf16(v.z, v.w);
    l.x = pack2_bf16(v.x - bf16_hi(v.x), v.y - bf16_hi(v.y));
    l.y = pack2_bf16(v.z - bf16_hi(v.z), v.w - bf16_hi(v.w));
    ((uint2*)hi)[i] = h;
    ((uint2*)lo)[i] = l;
}

// ===========================================================================
// Split-bf16 tensor-core GEMM with cp.async pipeline + ldmatrix.
// C[M,N] = A[M,K] @ B[N,K]^T + bias[N], A/B pre-split bf16 hi/lo.
// 128x128 CTA tile, BK=64, 256 threads (8 warps: 4M x 2N).
// mode 0: write fp32 C; mode 1: write split bf16 Chi/Clo.
// ===========================================================================
#define GS 72
#define GT (128 * GS)
#define GEMM_SMEM_B (8 * GT * 2)      // 2 stages x 4 tiles = 147456 B

__global__ __launch_bounds__(256, 1)
void mma_gemm_kernel(const __nv_bfloat16* __restrict__ Ah,
                     const __nv_bfloat16* __restrict__ Al,
                     const __nv_bfloat16* __restrict__ Bh,
                     const __nv_bfloat16* __restrict__ Bl,
                     const float* __restrict__ bias,
                     __nv_bfloat16* __restrict__ Chi,
                     __nv_bfloat16* __restrict__ Clo,
                     float* __restrict__ Cf,
                     int M, int N, int K, int mode)
{
    extern __shared__ __nv_bfloat16 sm[];
    const uint32_t sb = smem_u32(sm);

    const int t    = threadIdx.x;
    const int wid  = t >> 5;
    const int lane = t & 31;
    const int g    = lane >> 2;
    const int tq   = lane & 3;
    const int q    = lane >> 3;       // ldmatrix quad
    const int l8   = lane & 7;
    const int m0   = (wid >> 1) * 32;
    const int n0   = (wid & 1) * 64;

    const int bm = blockIdx.y * 128;
    const int bn = blockIdx.x * 128;

    float acc[2][8][4];
#pragma unroll
    for (int mi = 0; mi < 2; mi++)
#pragma unroll
        for (int ni = 0; ni < 8; ni++)
#pragma unroll
            for (int e = 0; e < 4; e++) acc[mi][ni][e] = 0.0f;

    const int NCHUNK = K / 64;

    // fill chunk c into stage s
    auto fill = [&](int c, int s) {
        const int k0 = c * 64;
        const uint32_t stg = s * 4 * GT;
#pragma unroll
        for (int i = 0; i < 4; i++) {
            const int l   = i * 256 + t;
            const int row = l >> 3;
            const int seg = l & 7;
            const uint32_t d = sb + 2 * (stg + row * GS + seg * 8);
            const size_t   o = (size_t)(bm + row) * K + k0 + seg * 8;
            const size_t   ob = (size_t)(bn + row) * K + k0 + seg * 8;
            cp16(d,              Ah + o);
            cp16(d + 2 * GT,     Al + o);
            cp16(d + 2 * 2 * GT, Bh + ob);
            cp16(d + 2 * 3 * GT, Bl + ob);
        }
    };

    fill(0, 0);
    CP_COMMIT();

    for (int c = 0; c < NCHUNK; c++) {
        if (c + 1 < NCHUNK) { fill(c + 1, (c + 1) & 1); CP_COMMIT(); CP_WAIT(1); }
        else                { CP_WAIT(0); }
        __syncthreads();

        const uint32_t stg = (c & 1) * 4 * GT;
        const uint32_t sAhi = sb + 2 * stg;
        const uint32_t sAlo = sAhi + 2 * GT;
        const uint32_t sBhi = sAlo + 2 * GT;
        const uint32_t sBlo = sBhi + 2 * GT;

#pragma unroll
        for (int ks = 0; ks < 4; ks++) {
            const int kk = ks * 16;
            uint32_t ah[2][4], al[2][4];
#pragma unroll
            for (int mi = 0; mi < 2; mi++) {
                const int arow = m0 + mi * 16 + (q & 1) * 8 + l8;
                const int acol = kk + (q >> 1) * 8;
                ldsm_x4(ah[mi], sAhi + 2 * (arow * GS + acol));
                ldsm_x4(al[mi], sAlo + 2 * (arow * GS + acol));
            }
#pragma unroll
            for (int np = 0; np < 4; np++) {
                const int brow = n0 + np * 16 + (q >> 1) * 8 + l8;
                const int bcol = kk + (q & 1) * 8;
                uint32_t bh[4], bl[4];
                ldsm_x4(bh, sBhi + 2 * (brow * GS + bcol));
                ldsm_x4(bl, sBlo + 2 * (brow * GS + bcol));
#pragma unroll
                for (int mi = 0; mi < 2; mi++) {
                    mma_bf16(acc[mi][2 * np],     ah[mi], bh);
                    mma_bf16(acc[mi][2 * np],     ah[mi], bl);
                    mma_bf16(acc[mi][2 * np],     al[mi], bh);
                    mma_bf16(acc[mi][2 * np + 1], ah[mi], bh + 2);
                    mma_bf16(acc[mi][2 * np + 1], ah[mi], bl + 2);
                    mma_bf16(acc[mi][2 * np + 1], al[mi], bh + 2);
                }
            }
        }
        __syncthreads();
    }

    // Epilogue
#pragma unroll
    for (int mi = 0; mi < 2; mi++) {
        const int r0 = bm + m0 + mi * 16 + g;
#pragma unroll
        for (int ni = 0; ni < 8; ni++) {
            const int col = bn + n0 + ni * 8 + 2 * tq;
            const float b0 = bias[col], b1 = bias[col + 1];
            float c00 = acc[mi][ni][0] + b0, c01 = acc[mi][ni][1] + b1;
            float c10 = acc[mi][ni][2] + b0, c11 = acc[mi][ni][3] + b1;
            if (mode == 0) {
                float2 v0 = {c00, c01}, v1 = {c10, c11};
                *(float2*)&Cf[(size_t)r0 * N + col]       = v0;
                *(float2*)&Cf[(size_t)(r0 + 8) * N + col] = v1;
            } else {
                *(uint32_t*)&Chi[(size_t)r0 * N + col] = pack2_bf16(c00, c01);
                *(uint32_t*)&Clo[(size_t)r0 * N + col] =
                    pack2_bf16(c00 - bf16_hi(c00), c01 - bf16_hi(c01));
                *(uint32_t*)&Chi[(size_t)(r0 + 8) * N + col] = pack2_bf16(c10, c11);
                *(uint32_t*)&Clo[(size_t)(r0 + 8) * N + col] =
                    pack2_bf16(c10 - bf16_hi(c10), c11 - bf16_hi(c11));
            }
        }
    }
}

// ===========================================================================
// FA2-style split-bf16 causal attention (no softmax).
// 8 warps x 16 q-rows. S in registers end-to-end; Q fragments in registers;
// K/V raw tiles via cp.async; V fragments via ldmatrix.trans.
// smem: Qhi Qlo Khi Klo Vhi Vlo, each [128][GS] bf16 (V raw [n][d]).
// ===========================================================================
#define AQ_HI 0
#define AQ_LO (GT)
#define AK_HI (2 * GT)
#define AK_LO (3 * GT)
#define AV_HI (4 * GT)
#define AV_LO (5 * GT)
#define ATTN_SMEM_B (6 * GT * 2)      // 110592 B

__global__ __launch_bounds__(256, 1)
void mma_attn_kernel(const __nv_bfloat16* __restrict__ Qh,
                     const __nv_bfloat16* __restrict__ Ql,
                     const __nv_bfloat16* __restrict__ Kh,
                     const __nv_bfloat16* __restrict__ Kl,
                     const __nv_bfloat16* __restrict__ Vh,
                     const __nv_bfloat16* __restrict__ Vl,
                     __nv_bfloat16* __restrict__ Ohi,
                     __nv_bfloat16* __restrict__ Olo)
{
    extern __shared__ __nv_bfloat16 sm[];
    const uint32_t sb = smem_u32(sm);

    const int qb = blockIdx.x;
    const int h  = blockIdx.y;
    const int b  = blockIdx.z;

    const int t    = threadIdx.x;
    const int wid  = t >> 5;
    const int lane = t & 31;
    const int g    = lane >> 2;
    const int tq   = lane & 3;
    const int q    = lane >> 3;
    const int l8   = lane & 7;
    const int m0   = wid * 16;          // warp's 16 q-rows within the 128-block

    const int hoff  = h * DH;
    const int brow0 = b * SEQ;          // batch row offset in [4096][1024] buffers
    const int qrow0 = brow0 + qb * 128;

    // ---- load Q tile via cp.async, then pull Q fragments into registers ----
#pragma unroll
    for (int i = 0; i < 4; i++) {
        const int l   = i * 256 + t;
        const int row = l >> 3;
        const int seg = l & 7;
        const uint32_t d = sb + 2 * (AQ_HI + row * GS + seg * 8);
        const size_t   o = (size_t)(qrow0 + row) * DMODEL + hoff + seg * 8;
        cp16(d,            Qh + o);
        cp16(d + 2 * GT,   Ql + o);
    }
    CP_COMMIT();
    CP_WAIT(0);
    __syncthreads();

    uint32_t qh[4][4], ql[4][4];
#pragma unroll
    for (int ks = 0; ks < 4; ks++) {
        const int arow = m0 + (q & 1) * 8 + l8;
        const int acol = ks * 16 + (q >> 1) * 8;
        ldsm_x4(qh[ks], sb + 2 * (AQ_HI + arow * GS + acol));
        ldsm_x4(ql[ks], sb + 2 * (AQ_LO + arow * GS + acol));
    }

    float o[8][4];
#pragma unroll
    for (int ni = 0; ni < 8; ni++)
#pragma unroll
        for (int e = 0; e < 4; e++) o[ni][e] = 0.0f;

    for (int kb = 0; kb <= qb; kb++) {
        __syncthreads();   // everyone done reading K/V of previous iteration

        // fill K and V (raw [n][d]) tiles
        const int krow0 = brow0 + kb * 128;
#pragma unroll
        for (int i = 0; i < 4; i++) {
            const int l   = i * 256 + t;
            const int row = l >> 3;
            const int seg = l & 7;
            const uint32_t d = sb + 2 * (AK_HI + row * GS + seg * 8);
            const size_t   s = (size_t)(krow0 + row) * DMODEL + hoff + seg * 8;
            cp16(d,              Kh + s);
            cp16(d + 2 * GT,     Kl + s);
            cp16(d + 2 * 2 * GT, Vh + s);
            cp16(d + 2 * 3 * GT, Vl + s);
        }
        CP_COMMIT();
        CP_WAIT(0);
        __syncthreads();

        // ---- Phase 1: S[16 x 128] fragments in registers ----
        float s[16][4];
#pragma unroll
        for (int nt = 0; nt < 16; nt++)
#pragma unroll
            for (int e = 0; e < 4; e++) s[nt][e] = 0.0f;

#pragma unroll
        for (int ks = 0; ks < 4; ks++) {
            const int kk = ks * 16;
#pragma unroll
            for (int ntp = 0; ntp < 8; ntp++) {
                const int brow = ntp * 16 + (q >> 1) * 8 + l8;
                const int bcol = kk + (q & 1) * 8;
                uint32_t bh[4], bl[4];
                ldsm_x4(bh, sb + 2 * (AK_HI + brow * GS + bcol));
                ldsm_x4(bl, sb + 2 * (AK_LO + brow * GS + bcol));
                mma_bf16(s[2 * ntp],     qh[ks], bh);
                mma_bf16(s[2 * ntp],     qh[ks], bl);
                mma_bf16(s[2 * ntp],     ql[ks], bh);
                mma_bf16(s[2 * ntp + 1], qh[ks], bh + 2);
                mma_bf16(s[2 * ntp + 1], qh[ks], bl + 2);
                mma_bf16(s[2 * ntp + 1], ql[ks], bh + 2);
            }
        }

        // Diagonal-block causal mask: keep col <= row
        if (kb == qb) {
            const int r0 = m0 + g, r1 = m0 + g + 8;
#pragma unroll
            for (int nt = 0; nt < 16; nt++) {
                const int c0 = nt * 8 + 2 * tq;
                if (c0     > r0) s[nt][0] = 0.0f;
                if (c0 + 1 > r0) s[nt][1] = 0.0f;
                if (c0     > r1) s[nt][2] = 0.0f;
                if (c0 + 1 > r1) s[nt][3] = 0.0f;
            }
        }

        // ---- Phase 2: O[16 x 64] += S @ V, A-fragments built from S regs ----
#pragma unroll
        for (int kc = 0; kc < 8; kc++) {
            uint32_t ah[4], al[4];
            {
                const float v0 = s[2 * kc][0],     v1 = s[2 * kc][1];
                const float v2 = s[2 * kc][2],     v3 = s[2 * kc][3];
                const float w0 = s[2 * kc + 1][0], w1 = s[2 * kc + 1][1];
                const float w2 = s[2 * kc + 1][2], w3 = s[2 * kc + 1][3];
                ah[0] = pack2_bf16(v0, v1);
                ah[1] = pack2_bf16(v2, v3);
                ah[2] = pack2_bf16(w0, w1);
                ah[3] = pack2_bf16(w2, w3);
                al[0] = pack2_bf16(v0 - bf16_hi(v0), v1 - bf16_hi(v1));
                al[1] = pack2_bf16(v2 - bf16_hi(v2), v3 - bf16_hi(v3));
                al[2] = pack2_bf16(w0 - bf16_hi(w0), w1 - bf16_hi(w1));
                al[3] = pack2_bf16(w2 - bf16_hi(w2), w3 - bf16_hi(w3));
            }
            const int kk = kc * 16;
#pragma unroll
            for (int ntp = 0; ntp < 4; ntp++) {
                const int vrow = kk + (q & 1) * 8 + l8;
                const int vcol = ntp * 16 + (q >> 1) * 8;
                uint32_t bh[4], bl[4];
                ldsm_x4_t(bh, sb + 2 * (AV_HI + vrow * GS + vcol));
                ldsm_x4_t(bl, sb + 2 * (AV_LO + vrow * GS + vcol));
                mma_bf16(o[2 * ntp],     ah, bh);
                mma_bf16(o[2 * ntp],     ah, bl);
                mma_bf16(o[2 * ntp],     al, bh);
                mma_bf16(o[2 * ntp + 1], ah, bh + 2);
                mma_bf16(o[2 * ntp + 1], ah, bl + 2);
                mma_bf16(o[2 * ntp + 1], al, bh + 2);
            }
        }
    }

    // Epilogue: write split-bf16 AO in concat-head layout
#pragma unroll
    for (int ni = 0; ni < 8; ni++) {
        const int col = hoff + ni * 8 + 2 * tq;
        const size_t r0 = (size_t)(qrow0 + m0 + g) * DMODEL + col;
        const size_t r1 = (size_t)(qrow0 + m0 + g + 8) * DMODEL + col;
        const float c00 = o[ni][0], c01 = o[ni][1];
        const float c10 = o[ni][2], c11 = o[ni][3];
        *(uint32_t*)&Ohi[r0] = pack2_bf16(c00, c01);
        *(uint32_t*)&Olo[r0] = pack2_bf16(c00 - bf16_hi(c00), c01 - bf16_hi(c01));
        *(uint32_t*)&Ohi[r1] = pack2_bf16(c10, c11);
        *(uint32_t*)&Olo[r1] = pack2_bf16(c10 - bf16_hi(c10), c11 - bf16_hi(c11));
    }
}

// ---------------------------------------------------------------------------
// Launch
// ---------------------------------------------------------------------------
extern "C" void kernel_launch(void* const* d_in, const int* in_sizes, int n_in,
                              void* d_out, int out_size)
{
    const float* x    = (const float*)d_in[0];
    const float* wq_w = (const float*)d_in[1];
    const float* wq_b = (const float*)d_in[2];
    const float* wk_w = (const float*)d_in[3];
    const float* wk_b = (const float*)d_in[4];
    const float* wv_w = (const float*)d_in[5];
    const float* wv_b = (const float*)d_in[6];
    const float* wo_w = (const float*)d_in[7];
    const float* wo_b = (const float*)d_in[8];
    float* out = (float*)d_out;

    __nv_bfloat16 *xhi, *xlo, *whi, *wlo;
    __nv_bfloat16 *Qhi, *Qlo, *Khi, *Klo, *Vhi, *Vlo, *AOhi, *AOlo;
    cudaGetSymbolAddress((void**)&xhi,  g_xhi);
    cudaGetSymbolAddress((void**)&xlo,  g_xlo);
    cudaGetSymbolAddress((void**)&whi,  g_whi);
    cudaGetSymbolAddress((void**)&wlo,  g_wlo);
    cudaGetSymbolAddress((void**)&Qhi,  g_Qhi);
    cudaGetSymbolAddress((void**)&Qlo,  g_Qlo);
    cudaGetSymbolAddress((void**)&Khi,  g_Khi);
    cudaGetSymbolAddress((void**)&Klo,  g_Klo);
    cudaGetSymbolAddress((void**)&Vhi,  g_Vhi);
    cudaGetSymbolAddress((void**)&Vlo,  g_Vlo);
    cudaGetSymbolAddress((void**)&AOhi, g_AOhi);
    cudaGetSymbolAddress((void**)&AOlo, g_AOlo);

    cudaFuncSetAttribute(mma_gemm_kernel,
                         cudaFuncAttributeMaxDynamicSharedMemorySize, GEMM_SMEM_B);
    cudaFuncSetAttribute(mma_attn_kernel,
                         cudaFuncAttributeMaxDynamicSharedMemorySize, ATTN_SMEM_B);

    const int WW = DMODEL * DMODEL;     // weight elements

    // Pre-split x and weights into bf16 hi/lo
    split_kernel<<<(MTOT * DMODEL / 4 + 255) / 256, 256>>>(x, xhi, xlo, MTOT * DMODEL / 4);
    split_kernel<<<(WW / 4 + 255) / 256, 256>>>(wq_w, whi + 0 * (size_t)WW, wlo + 0 * (size_t)WW, WW / 4);
    split_kernel<<<(WW / 4 + 255) / 256, 256>>>(wk_w, whi + 1 * (size_t)WW, wlo + 1 * (size_t)WW, WW / 4);
    split_kernel<<<(WW / 4 + 255) / 256, 256>>>(wv_w, whi + 2 * (size_t)WW, wlo + 2 * (size_t)WW, WW / 4);
    split_kernel<<<(WW / 4 + 255) / 256, 256>>>(wo_w, whi + 3 * (size_t)WW, wlo + 3 * (size_t)WW, WW / 4);

    dim3 ggrid(DMODEL / 128, MTOT / 128);   // (8, 32)
    mma_gemm_kernel<<<ggrid, 256, GEMM_SMEM_B>>>(
        xhi, xlo, whi + 0 * (size_t)WW, wlo + 0 * (size_t)WW, wq_b,
        Qhi, Qlo, nullptr, MTOT, DMODEL, DMODEL, 1);
    mma_gemm_kernel<<<ggrid, 256, GEMM_SMEM_B>>>(
        xhi, xlo, whi + 1 * (size_t)WW, wlo + 1 * (size_t)WW, wk_b,
        Khi, Klo, nullptr, MTOT, DMODEL, DMODEL, 1);
    mma_gemm_kernel<<<ggrid, 256, GEMM_SMEM_B>>>(
        xhi, xlo, whi + 2 * (size_t)WW, wlo + 2 * (size_t)WW, wv_b,
        Vhi, Vlo, nullptr, MTOT, DMODEL, DMODEL, 1);

    dim3 agrid(SEQ / 128, NH, BATCH);       // (16, 16, 2)
    mma_attn_kernel<<<agrid, 256, ATTN_SMEM_B>>>(Qhi, Qlo, Khi, Klo, Vhi, Vlo, AOhi, AOlo);

    mma_gemm_kernel<<<ggrid, 256, GEMM_SMEM_B>>>(
        AOhi, AOlo, whi + 3 * (size_t)WW, wlo + 3 * (size_t)WW, wo_b,
        nullptr, nullptr, out, MTOT, DMODEL, DMODEL, 0);
}

// round 8
// speedup vs baseline: 2.9133x; 1.0333x over previous
#include <cuda_runtime.h>
#include <cuda_bf16.h>
#include <cstdint>
#include <cstddef>

// Problem constants
#define BATCH   2
#define SEQ     2048
#define DMODEL  1024
#define NH      16
#define DH      64
#define MTOT    (BATCH * SEQ)        // 4096 rows

// ---------------------------------------------------------------------------
// Scratch (device globals; no allocations allowed)
// ---------------------------------------------------------------------------
__device__ __nv_bfloat16 g_xhi [MTOT * DMODEL];
__device__ __nv_bfloat16 g_xlo [MTOT * DMODEL];
__device__ __nv_bfloat16 g_whi [4][DMODEL * DMODEL];
__device__ __nv_bfloat16 g_wlo [4][DMODEL * DMODEL];
__device__ __nv_bfloat16 g_Qhi [MTOT * DMODEL];
__device__ __nv_bfloat16 g_Qlo [MTOT * DMODEL];
__device__ __nv_bfloat16 g_Khi [MTOT * DMODEL];
__device__ __nv_bfloat16 g_Klo [MTOT * DMODEL];
__device__ __nv_bfloat16 g_Vhi [MTOT * DMODEL];
__device__ __nv_bfloat16 g_Vlo [MTOT * DMODEL];
__device__ __nv_bfloat16 g_AOhi[MTOT * DMODEL];
__device__ __nv_bfloat16 g_AOlo[MTOT * DMODEL];

// ---------------------------------------------------------------------------
// Helpers
// ---------------------------------------------------------------------------
__device__ __forceinline__ void mma_bf16(float* c, const uint32_t* a, const uint32_t* b) {
    asm volatile(
        "mma.sync.aligned.m16n8k16.row.col.f32.bf16.bf16.f32 "
        "{%0,%1,%2,%3}, {%4,%5,%6,%7}, {%8,%9}, {%0,%1,%2,%3};"
        : "+f"(c[0]), "+f"(c[1]), "+f"(c[2]), "+f"(c[3])
        : "r"(a[0]), "r"(a[1]), "r"(a[2]), "r"(a[3]),
          "r"(b[0]), "r"(b[1]));
}

__device__ __forceinline__ uint32_t pack2_bf16(float a, float b) {
    __nv_bfloat162 t = __floats2bfloat162_rn(a, b);
    return *(uint32_t*)&t;
}
__device__ __forceinline__ float bf16_hi(float x) {
    return __bfloat162float(__float2bfloat16(x));
}

__device__ __forceinline__ uint32_t smem_u32(const void* p) {
    uint32_t a;
    asm("{ .reg .u64 t; cvta.to.shared.u64 t, %1; cvt.u32.u64 %0, t; }"
        : "=r"(a) : "l"(p));
    return a;
}

__device__ __forceinline__ void cp16(uint32_t dst, const void* src) {
    asm volatile("cp.async.cg.shared.global [%0], [%1], 16;" :: "r"(dst), "l"(src));
}
#define CP_COMMIT() asm volatile("cp.async.commit_group;" ::: "memory")
#define CP_WAIT(n)  asm volatile("cp.async.wait_group %0;" :: "n"(n) : "memory")

__device__ __forceinline__ void ldsm_x4(uint32_t* r, uint32_t addr) {
    asm volatile("ldmatrix.sync.aligned.m8n8.x4.shared.b16 {%0,%1,%2,%3}, [%4];"
        : "=r"(r[0]), "=r"(r[1]), "=r"(r[2]), "=r"(r[3]) : "r"(addr));
}
__device__ __forceinline__ void ldsm_x4_t(uint32_t* r, uint32_t addr) {
    asm volatile("ldmatrix.sync.aligned.m8n8.x4.trans.shared.b16 {%0,%1,%2,%3}, [%4];"
        : "=r"(r[0]), "=r"(r[1]), "=r"(r[2]), "=r"(r[3]) : "r"(addr));
}

// ---------------------------------------------------------------------------
// Split kernel: fp32 -> bf16 hi + bf16 lo residual
// ---------------------------------------------------------------------------
__global__ void split_kernel(const float* __restrict__ src,
                             __nv_bfloat16* __restrict__ hi,
                             __nv_bfloat16* __restrict__ lo, int n4)
{
    int i = blockIdx.x * blockDim.x + threadIdx.x;
    if (i >= n4) return;
    float4 v = ((const float4*)src)[i];
    uint2 h, l;
    h.x = pack2_bf16(v.x, v.y);
    h.y = pack2_bf16(v.z, v.w);
    l.x = pack2_bf16(v.x - bf16_hi(v.x), v.y - bf16_hi(v.y));
    l.y = pack2_bf16(v.z - bf16_hi(v.z), v.w - bf16_hi(v.w));
    ((uint2*)hi)[i] = h;
    ((uint2*)lo)[i] = l;
}

// ===========================================================================
// Split-bf16 tensor-core GEMM with cp.async pipeline + ldmatrix.
// C[M,N] = A[M,K] @ B[N,K]^T + bias[N], A/B pre-split bf16 hi/lo.
// 128x128 CTA tile, BK=64, 256 threads (8 warps: 4M x 2N).
// blockIdx.z selects {weight, bias, output} triple; mode 0 writes fp32.
// ===========================================================================
#define GS 72
#define GT (128 * GS)
#define GEMM_SMEM_B (8 * GT * 2)      // 2 stages x 4 tiles = 147456 B

__global__ __launch_bounds__(256, 1)
void mma_gemm_kernel(const __nv_bfloat16* __restrict__ Ah,
                     const __nv_bfloat16* __restrict__ Al,
                     const __nv_bfloat16* __restrict__ Wh,   // base of 3 stacked weights (or 1)
                     const __nv_bfloat16* __restrict__ Wl,
                     const float* __restrict__ b0,
                     const float* __restrict__ b1,
                     const float* __restrict__ b2,
                     __nv_bfloat16* __restrict__ C0h, __nv_bfloat16* __restrict__ C0l,
                     __nv_bfloat16* __restrict__ C1h, __nv_bfloat16* __restrict__ C1l,
                     __nv_bfloat16* __restrict__ C2h, __nv_bfloat16* __restrict__ C2l,
                     float* __restrict__ Cf,
                     int M, int N, int K, int mode)
{
    extern __shared__ __nv_bfloat16 sm[];
    const uint32_t sb = smem_u32(sm);

    const int z = blockIdx.z;
    const __nv_bfloat16* Bh = Wh + (size_t)z * DMODEL * DMODEL;
    const __nv_bfloat16* Bl = Wl + (size_t)z * DMODEL * DMODEL;
    const float* bias = (z == 0) ? b0 : (z == 1) ? b1 : b2;
    __nv_bfloat16* Chi = (z == 0) ? C0h : (z == 1) ? C1h : C2h;
    __nv_bfloat16* Clo = (z == 0) ? C0l : (z == 1) ? C1l : C2l;

    const int t    = threadIdx.x;
    const int wid  = t >> 5;
    const int lane = t & 31;
    const int g    = lane >> 2;
    const int tq   = lane & 3;
    const int q    = lane >> 3;       // ldmatrix quad
    const int l8   = lane & 7;
    const int m0   = (wid >> 1) * 32;
    const int n0   = (wid & 1) * 64;

    const int bm = blockIdx.y * 128;
    const int bn = blockIdx.x * 128;

    float acc[2][8][4];
#pragma unroll
    for (int mi = 0; mi < 2; mi++)
#pragma unroll
        for (int ni = 0; ni < 8; ni++)
#pragma unroll
            for (int e = 0; e < 4; e++) acc[mi][ni][e] = 0.0f;

    const int NCHUNK = K / 64;

    auto fill = [&](int c, int s) {
        const int k0 = c * 64;
        const uint32_t stg = s * 4 * GT;
#pragma unroll
        for (int i = 0; i < 4; i++) {
            const int l   = i * 256 + t;
            const int row = l >> 3;
            const int seg = l & 7;
            const uint32_t d = sb + 2 * (stg + row * GS + seg * 8);
            const size_t   o  = (size_t)(bm + row) * K + k0 + seg * 8;
            const size_t   ob = (size_t)(bn + row) * K + k0 + seg * 8;
            cp16(d,              Ah + o);
            cp16(d + 2 * GT,     Al + o);
            cp16(d + 2 * 2 * GT, Bh + ob);
            cp16(d + 2 * 3 * GT, Bl + ob);
        }
    };

    fill(0, 0);
    CP_COMMIT();

    for (int c = 0; c < NCHUNK; c++) {
        if (c + 1 < NCHUNK) { fill(c + 1, (c + 1) & 1); CP_COMMIT(); CP_WAIT(1); }
        else                { CP_WAIT(0); }
        __syncthreads();

        const uint32_t stg = (c & 1) * 4 * GT;
        const uint32_t sAhi = sb + 2 * stg;
        const uint32_t sAlo = sAhi + 2 * GT;
        const uint32_t sBhi = sAlo + 2 * GT;
        const uint32_t sBlo = sBhi + 2 * GT;

#pragma unroll
        for (int ks = 0; ks < 4; ks++) {
            const int kk = ks * 16;
            uint32_t ah[2][4], al[2][4];
#pragma unroll
            for (int mi = 0; mi < 2; mi++) {
                const int arow = m0 + mi * 16 + (q & 1) * 8 + l8;
                const int acol = kk + (q >> 1) * 8;
                ldsm_x4(ah[mi], sAhi + 2 * (arow * GS + acol));
                ldsm_x4(al[mi], sAlo + 2 * (arow * GS + acol));
            }
#pragma unroll
            for (int np = 0; np < 4; np++) {
                const int brow = n0 + np * 16 + (q >> 1) * 8 + l8;
                const int bcol = kk + (q & 1) * 8;
                uint32_t bh[4], bl[4];
                ldsm_x4(bh, sBhi + 2 * (brow * GS + bcol));
                ldsm_x4(bl, sBlo + 2 * (brow * GS + bcol));
#pragma unroll
                for (int mi = 0; mi < 2; mi++) {
                    mma_bf16(acc[mi][2 * np],     ah[mi], bh);
                    mma_bf16(acc[mi][2 * np],     ah[mi], bl);
                    mma_bf16(acc[mi][2 * np],     al[mi], bh);
                    mma_bf16(acc[mi][2 * np + 1], ah[mi], bh + 2);
                    mma_bf16(acc[mi][2 * np + 1], ah[mi], bl + 2);
                    mma_bf16(acc[mi][2 * np + 1], al[mi], bh + 2);
                }
            }
        }
        __syncthreads();
    }

    // Epilogue
#pragma unroll
    for (int mi = 0; mi < 2; mi++) {
        const int r0 = bm + m0 + mi * 16 + g;
#pragma unroll
        for (int ni = 0; ni < 8; ni++) {
            const int col = bn + n0 + ni * 8 + 2 * tq;
            const float bb0 = bias[col], bb1 = bias[col + 1];
            float c00 = acc[mi][ni][0] + bb0, c01 = acc[mi][ni][1] + bb1;
            float c10 = acc[mi][ni][2] + bb0, c11 = acc[mi][ni][3] + bb1;
            if (mode == 0) {
                float2 v0 = {c00, c01}, v1 = {c10, c11};
                *(float2*)&Cf[(size_t)r0 * N + col]       = v0;
                *(float2*)&Cf[(size_t)(r0 + 8) * N + col] = v1;
            } else {
                *(uint32_t*)&Chi[(size_t)r0 * N + col] = pack2_bf16(c00, c01);
                *(uint32_t*)&Clo[(size_t)r0 * N + col] =
                    pack2_bf16(c00 - bf16_hi(c00), c01 - bf16_hi(c01));
                *(uint32_t*)&Chi[(size_t)(r0 + 8) * N + col] = pack2_bf16(c10, c11);
                *(uint32_t*)&Clo[(size_t)(r0 + 8) * N + col] =
                    pack2_bf16(c10 - bf16_hi(c10), c11 - bf16_hi(c11));
            }
        }
    }
}

// ===========================================================================
// FA2-style split-bf16 causal attention, double-buffered K/V.
// 8 warps x 16 q-rows. S in registers end-to-end; Q fragments in registers.
// smem: Qhi Qlo + 2 stages x (Khi Klo Vhi Vlo) = 10 tiles = 184320 B.
// ===========================================================================
#define AQ_HI 0
#define AQ_LO (GT)
#define ATTN_STAGE(s) ((2 + 4 * (s)) * GT)
#define ATTN_SMEM_B (10 * GT * 2)     // 184320 B

__global__ __launch_bounds__(256, 1)
void mma_attn_kernel(const __nv_bfloat16* __restrict__ Qh,
                     const __nv_bfloat16* __restrict__ Ql,
                     const __nv_bfloat16* __restrict__ Kh,
                     const __nv_bfloat16* __restrict__ Kl,
                     const __nv_bfloat16* __restrict__ Vh,
                     const __nv_bfloat16* __restrict__ Vl,
                     __nv_bfloat16* __restrict__ Ohi,
                     __nv_bfloat16* __restrict__ Olo)
{
    extern __shared__ __nv_bfloat16 sm[];
    const uint32_t sb = smem_u32(sm);

    const int qb = (gridDim.x - 1) - blockIdx.x;   // heavy CTAs first
    const int h  = blockIdx.y;
    const int b  = blockIdx.z;

    const int t    = threadIdx.x;
    const int wid  = t >> 5;
    const int lane = t & 31;
    const int g    = lane >> 2;
    const int tq   = lane & 3;
    const int q    = lane >> 3;
    const int l8   = lane & 7;
    const int m0   = wid * 16;

    const int hoff  = h * DH;
    const int brow0 = b * SEQ;
    const int qrow0 = brow0 + qb * 128;

    auto fillKV = [&](int kb, int s) {
        const int krow0 = brow0 + kb * 128;
        const uint32_t st = ATTN_STAGE(s);
#pragma unroll
        for (int i = 0; i < 4; i++) {
            const int l   = i * 256 + t;
            const int row = l >> 3;
            const int seg = l & 7;
            const uint32_t d = sb + 2 * (st + row * GS + seg * 8);
            const size_t   sidx = (size_t)(krow0 + row) * DMODEL + hoff + seg * 8;
            cp16(d,              Kh + sidx);
            cp16(d + 2 * GT,     Kl + sidx);
            cp16(d + 2 * 2 * GT, Vh + sidx);
            cp16(d + 2 * 3 * GT, Vl + sidx);
        }
    };

    // ---- Q tile + first K/V stage in one async group ----
#pragma unroll
    for (int i = 0; i < 4; i++) {
        const int l   = i * 256 + t;
        const int row = l >> 3;
        const int seg = l & 7;
        const uint32_t d = sb + 2 * (AQ_HI + row * GS + seg * 8);
        const size_t   o = (size_t)(qrow0 + row) * DMODEL + hoff + seg * 8;
        cp16(d,          Qh + o);
        cp16(d + 2 * GT, Ql + o);
    }
    fillKV(0, 0);
    CP_COMMIT();
    CP_WAIT(0);
    __syncthreads();

    uint32_t qh[4][4], ql[4][4];
#pragma unroll
    for (int ks = 0; ks < 4; ks++) {
        const int arow = m0 + (q & 1) * 8 + l8;
        const int acol = ks * 16 + (q >> 1) * 8;
        ldsm_x4(qh[ks], sb + 2 * (AQ_HI + arow * GS + acol));
        ldsm_x4(ql[ks], sb + 2 * (AQ_LO + arow * GS + acol));
    }

    float o[8][4];
#pragma unroll
    for (int ni = 0; ni < 8; ni++)
#pragma unroll
        for (int e = 0; e < 4; e++) o[ni][e] = 0.0f;

    for (int kb = 0; kb <= qb; kb++) {
        // Prefetch next stage while this one computes
        if (kb + 1 <= qb) { fillKV(kb + 1, (kb + 1) & 1); CP_COMMIT(); CP_WAIT(1); }
        else              { CP_WAIT(0); }
        __syncthreads();   // this stage's data visible to all warps

        const uint32_t st   = ATTN_STAGE(kb & 1);
        const uint32_t sKhi = sb + 2 * st;
        const uint32_t sKlo = sKhi + 2 * GT;
        const uint32_t sVhi = sKlo + 2 * GT;
        const uint32_t sVlo = sVhi + 2 * GT;

        // ---- Phase 1: S[16 x 128] fragments in registers ----
        float s[16][4];
#pragma unroll
        for (int nt = 0; nt < 16; nt++)
#pragma unroll
            for (int e = 0; e < 4; e++) s[nt][e] = 0.0f;

#pragma unroll
        for (int ks = 0; ks < 4; ks++) {
            const int kk = ks * 16;
#pragma unroll
            for (int ntp = 0; ntp < 8; ntp++) {
                const int brow = ntp * 16 + (q >> 1) * 8 + l8;
                const int bcol = kk + (q & 1) * 8;
                uint32_t bh[4], bl[4];
                ldsm_x4(bh, sKhi + 2 * (brow * GS + bcol));
                ldsm_x4(bl, sKlo + 2 * (brow * GS + bcol));
                mma_bf16(s[2 * ntp],     qh[ks], bh);
                mma_bf16(s[2 * ntp],     qh[ks], bl);
                mma_bf16(s[2 * ntp],     ql[ks], bh);
                mma_bf16(s[2 * ntp + 1], qh[ks], bh + 2);
                mma_bf16(s[2 * ntp + 1], qh[ks], bl + 2);
                mma_bf16(s[2 * ntp + 1], ql[ks], bh + 2);
            }
        }

        // Diagonal-block causal mask: keep col <= row
        if (kb == qb) {
            const int r0 = m0 + g, r1 = m0 + g + 8;
#pragma unroll
            for (int nt = 0; nt < 16; nt++) {
                const int c0 = nt * 8 + 2 * tq;
                if (c0     > r0) s[nt][0] = 0.0f;
                if (c0 + 1 > r0) s[nt][1] = 0.0f;
                if (c0     > r1) s[nt][2] = 0.0f;
                if (c0 + 1 > r1) s[nt][3] = 0.0f;
            }
        }

        // ---- Phase 2: O[16 x 64] += S @ V ----
#pragma unroll
        for (int kc = 0; kc < 8; kc++) {
            uint32_t ah[4], al[4];
            {
                const float v0 = s[2 * kc][0],     v1 = s[2 * kc][1];
                const float v2 = s[2 * kc][2],     v3 = s[2 * kc][3];
                const float w0 = s[2 * kc + 1][0], w1 = s[2 * kc + 1][1];
                const float w2 = s[2 * kc + 1][2], w3 = s[2 * kc + 1][3];
                ah[0] = pack2_bf16(v0, v1);
                ah[1] = pack2_bf16(v2, v3);
                ah[2] = pack2_bf16(w0, w1);
                ah[3] = pack2_bf16(w2, w3);
                al[0] = pack2_bf16(v0 - bf16_hi(v0), v1 - bf16_hi(v1));
                al[1] = pack2_bf16(v2 - bf16_hi(v2), v3 - bf16_hi(v3));
                al[2] = pack2_bf16(w0 - bf16_hi(w0), w1 - bf16_hi(w1));
                al[3] = pack2_bf16(w2 - bf16_hi(w2), w3 - bf16_hi(w3));
            }
            const int kk = kc * 16;
#pragma unroll
            for (int ntp = 0; ntp < 4; ntp++) {
                const int vrow = kk + (q & 1) * 8 + l8;
                const int vcol = ntp * 16 + (q >> 1) * 8;
                uint32_t bh[4], bl[4];
                ldsm_x4_t(bh, sVhi + 2 * (vrow * GS + vcol));
                ldsm_x4_t(bl, sVlo + 2 * (vrow * GS + vcol));
                mma_bf16(o[2 * ntp],     ah, bh);
                mma_bf16(o[2 * ntp],     ah, bl);
                mma_bf16(o[2 * ntp],     al, bh);
                mma_bf16(o[2 * ntp + 1], ah, bh + 2);
                mma_bf16(o[2 * ntp + 1], ah, bl + 2);
                mma_bf16(o[2 * ntp + 1], al, bh + 2);
            }
        }
        __syncthreads();   // all warps done with this stage before it is refilled
    }

    // Epilogue: write split-bf16 AO in concat-head layout
#pragma unroll
    for (int ni = 0; ni < 8; ni++) {
        const int col = hoff + ni * 8 + 2 * tq;
        const size_t r0 = (size_t)(qrow0 + m0 + g) * DMODEL + col;
        const size_t r1 = (size_t)(qrow0 + m0 + g + 8) * DMODEL + col;
        const float c00 = o[ni][0], c01 = o[ni][1];
        const float c10 = o[ni][2], c11 = o[ni][3];
        *(uint32_t*)&Ohi[r0] = pack2_bf16(c00, c01);
        *(uint32_t*)&Olo[r0] = pack2_bf16(c00 - bf16_hi(c00), c01 - bf16_hi(c01));
        *(uint32_t*)&Ohi[r1] = pack2_bf16(c10, c11);
        *(uint32_t*)&Olo[r1] = pack2_bf16(c10 - bf16_hi(c10), c11 - bf16_hi(c11));
    }
}

// ---------------------------------------------------------------------------
// Launch
// ---------------------------------------------------------------------------
extern "C" void kernel_launch(void* const* d_in, const int* in_sizes, int n_in,
                              void* d_out, int out_size)
{
    const float* x    = (const float*)d_in[0];
    const float* wq_w = (const float*)d_in[1];
    const float* wq_b = (const float*)d_in[2];
    const float* wk_w = (const float*)d_in[3];
    const float* wk_b = (const float*)d_in[4];
    const float* wv_w = (const float*)d_in[5];
    const float* wv_b = (const float*)d_in[6];
    const float* wo_w = (const float*)d_in[7];
    const float* wo_b = (const float*)d_in[8];
    float* out = (float*)d_out;

    __nv_bfloat16 *xhi, *xlo, *whi, *wlo;
    __nv_bfloat16 *Qhi, *Qlo, *Khi, *Klo, *Vhi, *Vlo, *AOhi, *AOlo;
    cudaGetSymbolAddress((void**)&xhi,  g_xhi);
    cudaGetSymbolAddress((void**)&xlo,  g_xlo);
    cudaGetSymbolAddress((void**)&whi,  g_whi);
    cudaGetSymbolAddress((void**)&wlo,  g_wlo);
    cudaGetSymbolAddress((void**)&Qhi,  g_Qhi);
    cudaGetSymbolAddress((void**)&Qlo,  g_Qlo);
    cudaGetSymbolAddress((void**)&Khi,  g_Khi);
    cudaGetSymbolAddress((void**)&Klo,  g_Klo);
    cudaGetSymbolAddress((void**)&Vhi,  g_Vhi);
    cudaGetSymbolAddress((void**)&Vlo,  g_Vlo);
    cudaGetSymbolAddress((void**)&AOhi, g_AOhi);
    cudaGetSymbolAddress((void**)&AOlo, g_AOlo);

    cudaFuncSetAttribute(mma_gemm_kernel,
                         cudaFuncAttributeMaxDynamicSharedMemorySize, GEMM_SMEM_B);
    cudaFuncSetAttribute(mma_attn_kernel,
                         cudaFuncAttributeMaxDynamicSharedMemorySize, ATTN_SMEM_B);

    const size_t WW = (size_t)DMODEL * DMODEL;

    // Pre-split x and weights into bf16 hi/lo
    split_kernel<<<(MTOT * DMODEL / 4 + 255) / 256, 256>>>(x, xhi, xlo, MTOT * DMODEL / 4);
    split_kernel<<<((int)WW / 4 + 255) / 256, 256>>>(wq_w, whi + 0 * WW, wlo + 0 * WW, WW / 4);
    split_kernel<<<((int)WW / 4 + 255) / 256, 256>>>(wk_w, whi + 1 * WW, wlo + 1 * WW, WW / 4);
    split_kernel<<<((int)WW / 4 + 255) / 256, 256>>>(wv_w, whi + 2 * WW, wlo + 2 * WW, WW / 4);
    split_kernel<<<((int)WW / 4 + 255) / 256, 256>>>(wo_w, whi + 3 * WW, wlo + 3 * WW, WW / 4);

    // Fused Q/K/V projections: grid z = 3
    dim3 gqkv(DMODEL / 128, MTOT / 128, 3);
    mma_gemm_kernel<<<gqkv, 256, GEMM_SMEM_B>>>(
        xhi, xlo, whi, wlo, wq_b, wk_b, wv_b,
        Qhi, Qlo, Khi, Klo, Vhi, Vlo, nullptr,
        MTOT, DMODEL, DMODEL, 1);

    dim3 agrid(SEQ / 128, NH, BATCH);
    mma_attn_kernel<<<agrid, 256, ATTN_SMEM_B>>>(Qhi, Qlo, Khi, Klo, Vhi, Vlo, AOhi, AOlo);

    dim3 ggrid(DMODEL / 128, MTOT / 128, 1);
    mma_gemm_kernel<<<ggrid, 256, GEMM_SMEM_B>>>(
        AOhi, AOlo, whi + 3 * WW, wlo + 3 * WW, wo_b, nullptr, nullptr,
        nullptr, nullptr, nullptr, nullptr, nullptr, nullptr, out,
        MTOT, DMODEL, DMODEL, 0);
}

// round 9
// speedup vs baseline: 2.9532x; 1.0137x over previous
#include <cuda_runtime.h>
#include <cuda_bf16.h>
#include <cstdint>
#include <cstddef>

// Problem constants
#define BATCH   2
#define SEQ     2048
#define DMODEL  1024
#define NH      16
#define DH      64
#define MTOT    (BATCH * SEQ)        // 4096 rows

// ---------------------------------------------------------------------------
// Scratch (device globals; no allocations allowed)
// ---------------------------------------------------------------------------
__device__ __nv_bfloat16 g_xhi [MTOT * DMODEL];
__device__ __nv_bfloat16 g_xlo [MTOT * DMODEL];
__device__ __nv_bfloat16 g_whi [4][DMODEL * DMODEL];
__device__ __nv_bfloat16 g_wlo [4][DMODEL * DMODEL];
__device__ __nv_bfloat16 g_Qhi [MTOT * DMODEL];
__device__ __nv_bfloat16 g_Qlo [MTOT * DMODEL];
__device__ __nv_bfloat16 g_Khi [MTOT * DMODEL];
__device__ __nv_bfloat16 g_Klo [MTOT * DMODEL];
__device__ __nv_bfloat16 g_Vhi [MTOT * DMODEL];
__device__ __nv_bfloat16 g_Vlo [MTOT * DMODEL];
__device__ __nv_bfloat16 g_AOhi[MTOT * DMODEL];
__device__ __nv_bfloat16 g_AOlo[MTOT * DMODEL];

// ---------------------------------------------------------------------------
// Helpers
// ---------------------------------------------------------------------------
__device__ __forceinline__ void mma_bf16(float* c, const uint32_t* a, const uint32_t* b) {
    asm volatile(
        "mma.sync.aligned.m16n8k16.row.col.f32.bf16.bf16.f32 "
        "{%0,%1,%2,%3}, {%4,%5,%6,%7}, {%8,%9}, {%0,%1,%2,%3};"
        : "+f"(c[0]), "+f"(c[1]), "+f"(c[2]), "+f"(c[3])
        : "r"(a[0]), "r"(a[1]), "r"(a[2]), "r"(a[3]),
          "r"(b[0]), "r"(b[1]));
}

__device__ __forceinline__ uint32_t pack2_bf16(float a, float b) {
    __nv_bfloat162 t = __floats2bfloat162_rn(a, b);
    return *(uint32_t*)&t;
}
__device__ __forceinline__ float bf16_hi(float x) {
    return __bfloat162float(__float2bfloat16(x));
}

__device__ __forceinline__ uint32_t smem_u32(const void* p) {
    uint32_t a;
    asm("{ .reg .u64 t; cvta.to.shared.u64 t, %1; cvt.u32.u64 %0, t; }"
        : "=r"(a) : "l"(p));
    return a;
}

__device__ __forceinline__ void cp16(uint32_t dst, const void* src) {
    asm volatile("cp.async.cg.shared.global [%0], [%1], 16;" :: "r"(dst), "l"(src));
}
#define CP_COMMIT() asm volatile("cp.async.commit_group;" ::: "memory")
#define CP_WAIT(n)  asm volatile("cp.async.wait_group %0;" :: "n"(n) : "memory")

__device__ __forceinline__ void ldsm_x4(uint32_t* r, uint32_t addr) {
    asm volatile("ldmatrix.sync.aligned.m8n8.x4.shared.b16 {%0,%1,%2,%3}, [%4];"
        : "=r"(r[0]), "=r"(r[1]), "=r"(r[2]), "=r"(r[3]) : "r"(addr));
}
__device__ __forceinline__ void ldsm_x4_t(uint32_t* r, uint32_t addr) {
    asm volatile("ldmatrix.sync.aligned.m8n8.x4.trans.shared.b16 {%0,%1,%2,%3}, [%4];"
        : "=r"(r[0]), "=r"(r[1]), "=r"(r[2]), "=r"(r[3]) : "r"(addr));
}

// ---------------------------------------------------------------------------
// Split kernel: fp32 -> bf16 hi + bf16 lo residual
// ---------------------------------------------------------------------------
__global__ void split_kernel(const float* __restrict__ src,
                             __nv_bfloat16* __restrict__ hi,
                             __nv_bfloat16* __restrict__ lo, int n4)
{
    int i = blockIdx.x * blockDim.x + threadIdx.x;
    if (i >= n4) return;
    float4 v = ((const float4*)src)[i];
    uint2 h, l;
    h.x = pack2_bf16(v.x, v.y);
    h.y = pack2_bf16(v.z, v.w);
    l.x = pack2_bf16(v.x - bf16_hi(v.x), v.y - bf16_hi(v.y));
    l.y = pack2_bf16(v.z - bf16_hi(v.z), v.w - bf16_hi(v.w));
    ((uint2*)hi)[i] = h;
    ((uint2*)lo)[i] = l;
}

// ===========================================================================
// Split-bf16 GEMM, 3-stage cp.async ring, pass-reordered MMAs.
// C[M,N] = A[M,K] @ B[N,K]^T + bias[N]. 128x128 CTA, BK=64, 8 warps (4Mx2N).
// ===========================================================================
#define GS 72
#define GT (128 * GS)
#define GEMM_SMEM_B (12 * GT * 2)     // 3 stages x 4 tiles = 221184 B

__global__ __launch_bounds__(256, 1)
void mma_gemm_kernel(const __nv_bfloat16* __restrict__ Ah,
                     const __nv_bfloat16* __restrict__ Al,
                     const __nv_bfloat16* __restrict__ Wh,
                     const __nv_bfloat16* __restrict__ Wl,
                     const float* __restrict__ b0,
                     const float* __restrict__ b1,
                     const float* __restrict__ b2,
                     __nv_bfloat16* __restrict__ C0h, __nv_bfloat16* __restrict__ C0l,
                     __nv_bfloat16* __restrict__ C1h, __nv_bfloat16* __restrict__ C1l,
                     __nv_bfloat16* __restrict__ C2h, __nv_bfloat16* __restrict__ C2l,
                     float* __restrict__ Cf,
                     int M, int N, int K, int mode)
{
    extern __shared__ __nv_bfloat16 sm[];
    const uint32_t sb = smem_u32(sm);

    const int z = blockIdx.z;
    const __nv_bfloat16* Bh = Wh + (size_t)z * DMODEL * DMODEL;
    const __nv_bfloat16* Bl = Wl + (size_t)z * DMODEL * DMODEL;
    const float* bias = (z == 0) ? b0 : (z == 1) ? b1 : b2;
    __nv_bfloat16* Chi = (z == 0) ? C0h : (z == 1) ? C1h : C2h;
    __nv_bfloat16* Clo = (z == 0) ? C0l : (z == 1) ? C1l : C2l;

    const int t    = threadIdx.x;
    const int wid  = t >> 5;
    const int lane = t & 31;
    const int g    = lane >> 2;
    const int tq   = lane & 3;
    const int q    = lane >> 3;
    const int l8   = lane & 7;
    const int m0   = (wid >> 1) * 32;
    const int n0   = (wid & 1) * 64;

    const int bm = blockIdx.y * 128;
    const int bn = blockIdx.x * 128;

    float acc[2][8][4];
#pragma unroll
    for (int mi = 0; mi < 2; mi++)
#pragma unroll
        for (int ni = 0; ni < 8; ni++)
#pragma unroll
            for (int e = 0; e < 4; e++) acc[mi][ni][e] = 0.0f;

    const int NCHUNK = K / 64;    // 16

    auto fill = [&](int c, int s) {
        const int k0 = c * 64;
        const uint32_t stg = s * 4 * GT;
#pragma unroll
        for (int i = 0; i < 4; i++) {
            const int l   = i * 256 + t;
            const int row = l >> 3;
            const int seg = l & 7;
            const uint32_t d = sb + 2 * (stg + row * GS + seg * 8);
            const size_t   o  = (size_t)(bm + row) * K + k0 + seg * 8;
            const size_t   ob = (size_t)(bn + row) * K + k0 + seg * 8;
            cp16(d,              Ah + o);
            cp16(d + 2 * GT,     Al + o);
            cp16(d + 2 * 2 * GT, Bh + ob);
            cp16(d + 2 * 3 * GT, Bl + ob);
        }
    };

    fill(0, 0); CP_COMMIT();
    fill(1, 1); CP_COMMIT();

    for (int c = 0; c < NCHUNK; c++) {
        if (c == NCHUNK - 1) { CP_WAIT(0); } else { CP_WAIT(1); }
        __syncthreads();
        if (c + 2 < NCHUNK) { fill(c + 2, (c + 2) % 3); CP_COMMIT(); }

        const uint32_t stg  = (c % 3) * 4 * GT;
        const uint32_t sAhi = sb + 2 * stg;
        const uint32_t sAlo = sAhi + 2 * GT;
        const uint32_t sBhi = sAlo + 2 * GT;
        const uint32_t sBlo = sBhi + 2 * GT;

#pragma unroll
        for (int ks = 0; ks < 4; ks++) {
            const int kk = ks * 16;

            uint32_t ah[2][4], al[2][4];
#pragma unroll
            for (int mi = 0; mi < 2; mi++) {
                const int arow = m0 + mi * 16 + (q & 1) * 8 + l8;
                const int acol = kk + (q >> 1) * 8;
                ldsm_x4(ah[mi], sAhi + 2 * (arow * GS + acol));
                ldsm_x4(al[mi], sAlo + 2 * (arow * GS + acol));
            }
            uint32_t bh[4][4], bl[4][4];
#pragma unroll
            for (int np = 0; np < 4; np++) {
                const int brow = n0 + np * 16 + (q >> 1) * 8 + l8;
                const int bcol = kk + (q & 1) * 8;
                ldsm_x4(bh[np], sBhi + 2 * (brow * GS + bcol));
                ldsm_x4(bl[np], sBlo + 2 * (brow * GS + bcol));
            }

            // pass hh (16 independent MMAs)
#pragma unroll
            for (int mi = 0; mi < 2; mi++)
#pragma unroll
                for (int np = 0; np < 4; np++) {
                    mma_bf16(acc[mi][2 * np],     ah[mi], bh[np]);
                    mma_bf16(acc[mi][2 * np + 1], ah[mi], bh[np] + 2);
                }
            // pass hl
#pragma unroll
            for (int mi = 0; mi < 2; mi++)
#pragma unroll
                for (int np = 0; np < 4; np++) {
                    mma_bf16(acc[mi][2 * np],     ah[mi], bl[np]);
                    mma_bf16(acc[mi][2 * np + 1], ah[mi], bl[np] + 2);
                }
            // pass lh
#pragma unroll
            for (int mi = 0; mi < 2; mi++)
#pragma unroll
                for (int np = 0; np < 4; np++) {
                    mma_bf16(acc[mi][2 * np],     al[mi], bh[np]);
                    mma_bf16(acc[mi][2 * np + 1], al[mi], bh[np] + 2);
                }
        }
    }

    // Epilogue
#pragma unroll
    for (int mi = 0; mi < 2; mi++) {
        const int r0 = bm + m0 + mi * 16 + g;
#pragma unroll
        for (int ni = 0; ni < 8; ni++) {
            const int col = bn + n0 + ni * 8 + 2 * tq;
            const float bb0 = bias[col], bb1 = bias[col + 1];
            float c00 = acc[mi][ni][0] + bb0, c01 = acc[mi][ni][1] + bb1;
            float c10 = acc[mi][ni][2] + bb0, c11 = acc[mi][ni][3] + bb1;
            if (mode == 0) {
                float2 v0 = {c00, c01}, v1 = {c10, c11};
                *(float2*)&Cf[(size_t)r0 * N + col]       = v0;
                *(float2*)&Cf[(size_t)(r0 + 8) * N + col] = v1;
            } else {
                *(uint32_t*)&Chi[(size_t)r0 * N + col] = pack2_bf16(c00, c01);
                *(uint32_t*)&Clo[(size_t)r0 * N + col] =
                    pack2_bf16(c00 - bf16_hi(c00), c01 - bf16_hi(c01));
                *(uint32_t*)&Chi[(size_t)(r0 + 8) * N + col] = pack2_bf16(c10, c11);
                *(uint32_t*)&Clo[(size_t)(r0 + 8) * N + col] =
                    pack2_bf16(c10 - bf16_hi(c10), c11 - bf16_hi(c11));
            }
        }
    }
}

// ===========================================================================
// FA2-style split-bf16 causal attention, 3-stage K/V ring (reuses Q tiles),
// pass-reordered MMAs. 8 warps x 16 q-rows; S and Q in registers.
// smem: 12 tiles of GT halves. Q stages in tiles 0,1 (prologue only);
// ring: stage0 K@2 V@4, stage1 K@6 V@8, stage2 K@10 V@0.
// ===========================================================================
#define ATTN_SMEM_B (12 * GT * 2)     // 221184 B

__global__ __launch_bounds__(256, 1)
void mma_attn_kernel(const __nv_bfloat16* __restrict__ Qh,
                     const __nv_bfloat16* __restrict__ Ql,
                     const __nv_bfloat16* __restrict__ Kh,
                     const __nv_bfloat16* __restrict__ Kl,
                     const __nv_bfloat16* __restrict__ Vh,
                     const __nv_bfloat16* __restrict__ Vl,
                     __nv_bfloat16* __restrict__ Ohi,
                     __nv_bfloat16* __restrict__ Olo)
{
    extern __shared__ __nv_bfloat16 sm[];
    const uint32_t sb = smem_u32(sm);

    const int qb = (gridDim.x - 1) - blockIdx.x;   // heavy CTAs first
    const int h  = blockIdx.y;
    const int b  = blockIdx.z;

    const int t    = threadIdx.x;
    const int wid  = t >> 5;
    const int lane = t & 31;
    const int g    = lane >> 2;
    const int tq   = lane & 3;
    const int q    = lane >> 3;
    const int l8   = lane & 7;
    const int m0   = wid * 16;

    const int hoff  = h * DH;
    const int brow0 = b * SEQ;
    const int qrow0 = brow0 + qb * 128;

    // ring tile bases (in halves)
    const uint32_t stK[3] = { 2u * GT, 6u * GT, 10u * GT };
    const uint32_t stV[3] = { 4u * GT, 8u * GT, 0u * GT  };

    auto fillKV = [&](int kb, int s) {
        const int krow0 = brow0 + kb * 128;
#pragma unroll
        for (int i = 0; i < 4; i++) {
            const int l   = i * 256 + t;
            const int row = l >> 3;
            const int seg = l & 7;
            const uint32_t off = row * GS + seg * 8;
            const size_t   sidx = (size_t)(krow0 + row) * DMODEL + hoff + seg * 8;
            const uint32_t dK = sb + 2 * (stK[s] + off);
            const uint32_t dV = sb + 2 * (stV[s] + off);
            cp16(dK,          Kh + sidx);
            cp16(dK + 2 * GT, Kl + sidx);
            cp16(dV,          Vh + sidx);
            cp16(dV + 2 * GT, Vl + sidx);
        }
    };

    // ---- prologue: Q (tiles 0,1) + KV stage 0 as group 0; KV stage 1 group 1
#pragma unroll
    for (int i = 0; i < 4; i++) {
        const int l   = i * 256 + t;
        const int row = l >> 3;
        const int seg = l & 7;
        const uint32_t d = sb + 2 * (row * GS + seg * 8);
        const size_t   o = (size_t)(qrow0 + row) * DMODEL + hoff + seg * 8;
        cp16(d,          Qh + o);
        cp16(d + 2 * GT, Ql + o);
    }
    fillKV(0, 0);
    CP_COMMIT();
    if (qb >= 1) { fillKV(1, 1); CP_COMMIT(); }

    if (qb >= 1) { CP_WAIT(1); } else { CP_WAIT(0); }
    __syncthreads();

    uint32_t qh[4][4], ql[4][4];
#pragma unroll
    for (int ks = 0; ks < 4; ks++) {
        const int arow = m0 + (q & 1) * 8 + l8;
        const int acol = ks * 16 + (q >> 1) * 8;
        ldsm_x4(qh[ks], sb + 2 * (arow * GS + acol));
        ldsm_x4(ql[ks], sb + 2 * (GT + arow * GS + acol));
    }

    float o[8][4];
#pragma unroll
    for (int ni = 0; ni < 8; ni++)
#pragma unroll
        for (int e = 0; e < 4; e++) o[ni][e] = 0.0f;

    for (int kb = 0; kb <= qb; kb++) {
        if (kb == qb) { CP_WAIT(0); } else { CP_WAIT(1); }
        __syncthreads();
        if (kb + 2 <= qb) { fillKV(kb + 2, (kb + 2) % 3); CP_COMMIT(); }

        const int st = kb % 3;
        const uint32_t sKhi = sb + 2 * stK[st];
        const uint32_t sKlo = sKhi + 2 * GT;
        const uint32_t sVhi = sb + 2 * stV[st];
        const uint32_t sVlo = sVhi + 2 * GT;

        // ---- Phase 1: S[16 x 128] in registers ----
        float s[16][4];
#pragma unroll
        for (int nt = 0; nt < 16; nt++)
#pragma unroll
            for (int e = 0; e < 4; e++) s[nt][e] = 0.0f;

#pragma unroll
        for (int ks = 0; ks < 4; ks++) {
            const int kk = ks * 16;
#pragma unroll
            for (int half = 0; half < 2; half++) {
                uint32_t bh[4][4], bl[4][4];
#pragma unroll
                for (int j = 0; j < 4; j++) {
                    const int ntp = half * 4 + j;
                    const int brow = ntp * 16 + (q >> 1) * 8 + l8;
                    const int bcol = kk + (q & 1) * 8;
                    ldsm_x4(bh[j], sKhi + 2 * (brow * GS + bcol));
                    ldsm_x4(bl[j], sKlo + 2 * (brow * GS + bcol));
                }
                // pass hh (8 independent)
#pragma unroll
                for (int j = 0; j < 4; j++) {
                    const int nt = (half * 4 + j) * 2;
                    mma_bf16(s[nt],     qh[ks], bh[j]);
                    mma_bf16(s[nt + 1], qh[ks], bh[j] + 2);
                }
                // pass hl
#pragma unroll
                for (int j = 0; j < 4; j++) {
                    const int nt = (half * 4 + j) * 2;
                    mma_bf16(s[nt],     qh[ks], bl[j]);
                    mma_bf16(s[nt + 1], qh[ks], bl[j] + 2);
                }
                // pass lh
#pragma unroll
                for (int j = 0; j < 4; j++) {
                    const int nt = (half * 4 + j) * 2;
                    mma_bf16(s[nt],     ql[ks], bh[j]);
                    mma_bf16(s[nt + 1], ql[ks], bh[j] + 2);
                }
            }
        }

        // Diagonal-block causal mask: keep col <= row
        if (kb == qb) {
            const int r0 = m0 + g, r1 = m0 + g + 8;
#pragma unroll
            for (int nt = 0; nt < 16; nt++) {
                const int c0 = nt * 8 + 2 * tq;
                if (c0     > r0) s[nt][0] = 0.0f;
                if (c0 + 1 > r0) s[nt][1] = 0.0f;
                if (c0     > r1) s[nt][2] = 0.0f;
                if (c0 + 1 > r1) s[nt][3] = 0.0f;
            }
        }

        // ---- Phase 2: O[16 x 64] += S @ V ----
#pragma unroll
        for (int kc = 0; kc < 8; kc++) {
            uint32_t ah[4], al[4];
            {
                const float v0 = s[2 * kc][0],     v1 = s[2 * kc][1];
                const float v2 = s[2 * kc][2],     v3 = s[2 * kc][3];
                const float w0 = s[2 * kc + 1][0], w1 = s[2 * kc + 1][1];
                const float w2 = s[2 * kc + 1][2], w3 = s[2 * kc + 1][3];
                ah[0] = pack2_bf16(v0, v1);
                ah[1] = pack2_bf16(v2, v3);
                ah[2] = pack2_bf16(w0, w1);
                ah[3] = pack2_bf16(w2, w3);
                al[0] = pack2_bf16(v0 - bf16_hi(v0), v1 - bf16_hi(v1));
                al[1] = pack2_bf16(v2 - bf16_hi(v2), v3 - bf16_hi(v3));
                al[2] = pack2_bf16(w0 - bf16_hi(w0), w1 - bf16_hi(w1));
                al[3] = pack2_bf16(w2 - bf16_hi(w2), w3 - bf16_hi(w3));
            }
            const int kk = kc * 16;
            uint32_t bh[4][4], bl[4][4];
#pragma unroll
            for (int ntp = 0; ntp < 4; ntp++) {
                const int vrow = kk + (q & 1) * 8 + l8;
                const int vcol = ntp * 16 + (q >> 1) * 8;
                ldsm_x4_t(bh[ntp], sVhi + 2 * (vrow * GS + vcol));
                ldsm_x4_t(bl[ntp], sVlo + 2 * (vrow * GS + vcol));
            }
            // pass hh (8 independent)
#pragma unroll
            for (int ntp = 0; ntp < 4; ntp++) {
                mma_bf16(o[2 * ntp],     ah, bh[ntp]);
                mma_bf16(o[2 * ntp + 1], ah, bh[ntp] + 2);
            }
            // pass hl
#pragma unroll
            for (int ntp = 0; ntp < 4; ntp++) {
                mma_bf16(o[2 * ntp],     ah, bl[ntp]);
                mma_bf16(o[2 * ntp + 1], ah, bl[ntp] + 2);
            }
            // pass lh
#pragma unroll
            for (int ntp = 0; ntp < 4; ntp++) {
                mma_bf16(o[2 * ntp],     al, bh[ntp]);
                mma_bf16(o[2 * ntp + 1], al, bh[ntp] + 2);
            }
        }
    }

    // Epilogue: write split-bf16 AO in concat-head layout
#pragma unroll
    for (int ni = 0; ni < 8; ni++) {
        const int col = hoff + ni * 8 + 2 * tq;
        const size_t r0 = (size_t)(qrow0 + m0 + g) * DMODEL + col;
        const size_t r1 = (size_t)(qrow0 + m0 + g + 8) * DMODEL + col;
        const float c00 = o[ni][0], c01 = o[ni][1];
        const float c10 = o[ni][2], c11 = o[ni][3];
        *(uint32_t*)&Ohi[r0] = pack2_bf16(c00, c01);
        *(uint32_t*)&Olo[r0] = pack2_bf16(c00 - bf16_hi(c00), c01 - bf16_hi(c01));
        *(uint32_t*)&Ohi[r1] = pack2_bf16(c10, c11);
        *(uint32_t*)&Olo[r1] = pack2_bf16(c10 - bf16_hi(c10), c11 - bf16_hi(c11));
    }
}

// ---------------------------------------------------------------------------
// Launch
// ---------------------------------------------------------------------------
extern "C" void kernel_launch(void* const* d_in, const int* in_sizes, int n_in,
                              void* d_out, int out_size)
{
    const float* x    = (const float*)d_in[0];
    const float* wq_w = (const float*)d_in[1];
    const float* wq_b = (const float*)d_in[2];
    const float* wk_w = (const float*)d_in[3];
    const float* wk_b = (const float*)d_in[4];
    const float* wv_w = (const float*)d_in[5];
    const float* wv_b = (const float*)d_in[6];
    const float* wo_w = (const float*)d_in[7];
    const float* wo_b = (const float*)d_in[8];
    float* out = (float*)d_out;

    __nv_bfloat16 *xhi, *xlo, *whi, *wlo;
    __nv_bfloat16 *Qhi, *Qlo, *Khi, *Klo, *Vhi, *Vlo, *AOhi, *AOlo;
    cudaGetSymbolAddress((void**)&xhi,  g_xhi);
    cudaGetSymbolAddress((void**)&xlo,  g_xlo);
    cudaGetSymbolAddress((void**)&whi,  g_whi);
    cudaGetSymbolAddress((void**)&wlo,  g_wlo);
    cudaGetSymbolAddress((void**)&Qhi,  g_Qhi);
    cudaGetSymbolAddress((void**)&Qlo,  g_Qlo);
    cudaGetSymbolAddress((void**)&Khi,  g_Khi);
    cudaGetSymbolAddress((void**)&Klo,  g_Klo);
    cudaGetSymbolAddress((void**)&Vhi,  g_Vhi);
    cudaGetSymbolAddress((void**)&Vlo,  g_Vlo);
    cudaGetSymbolAddress((void**)&AOhi, g_AOhi);
    cudaGetSymbolAddress((void**)&AOlo, g_AOlo);

    cudaFuncSetAttribute(mma_gemm_kernel,
                         cudaFuncAttributeMaxDynamicSharedMemorySize, GEMM_SMEM_B);
    cudaFuncSetAttribute(mma_attn_kernel,
                         cudaFuncAttributeMaxDynamicSharedMemorySize, ATTN_SMEM_B);

    const size_t WW = (size_t)DMODEL * DMODEL;

    split_kernel<<<(MTOT * DMODEL / 4 + 255) / 256, 256>>>(x, xhi, xlo, MTOT * DMODEL / 4);
    split_kernel<<<((int)WW / 4 + 255) / 256, 256>>>(wq_w, whi + 0 * WW, wlo + 0 * WW, WW / 4);
    split_kernel<<<((int)WW / 4 + 255) / 256, 256>>>(wk_w, whi + 1 * WW, wlo + 1 * WW, WW / 4);
    split_kernel<<<((int)WW / 4 + 255) / 256, 256>>>(wv_w, whi + 2 * WW, wlo + 2 * WW, WW / 4);
    split_kernel<<<((int)WW / 4 + 255) / 256, 256>>>(wo_w, whi + 3 * WW, wlo + 3 * WW, WW / 4);

    // Fused Q/K/V projections
    dim3 gqkv(DMODEL / 128, MTOT / 128, 3);
    mma_gemm_kernel<<<gqkv, 256, GEMM_SMEM_B>>>(
        xhi, xlo, whi, wlo, wq_b, wk_b, wv_b,
        Qhi, Qlo, Khi, Klo, Vhi, Vlo, nullptr,
        MTOT, DMODEL, DMODEL, 1);

    dim3 agrid(SEQ / 128, NH, BATCH);
    mma_attn_kernel<<<agrid, 256, ATTN_SMEM_B>>>(Qhi, Qlo, Khi, Klo, Vhi, Vlo, AOhi, AOlo);

    dim3 ggrid(DMODEL / 128, MTOT / 128, 1);
    mma_gemm_kernel<<<ggrid, 256, GEMM_SMEM_B>>>(
        AOhi, AOlo, whi + 3 * WW, wlo + 3 * WW, wo_b, nullptr, nullptr,
        nullptr, nullptr, nullptr, nullptr, nullptr, nullptr, out,
        MTOT, DMODEL, DMODEL, 0);
}